// round 1
// baseline (speedup 1.0000x reference)
#include <cuda_runtime.h>
#include <math.h>

#define D_M   1024
#define NH    16
#define HD    64
#define BATCH 4
#define SEQ   2048
#define MTOT  (BATCH*SEQ)

// Scratch (device globals -- no allocation allowed in kernel_launch)
__device__ float g_q[(size_t)BATCH*NH*SEQ*HD];   // [B,H,S,hd]
__device__ float g_k[(size_t)BATCH*NH*SEQ*HD];
__device__ float g_v[(size_t)BATCH*NH*SEQ*HD];
__device__ float g_y[(size_t)MTOT*D_M];          // [B,S,D] attention output

// ---------------------------------------------------------------------------
// GEMM: out[m,n] = sum_k A[m,k] * W[n,k] + bias[n]
// A: [M,1024] row-major, W: [1024,1024] row-major (nn.Linear weight)
// mode 0: scatter into [B,H,S,hd] layout (QKV), mode 1: row-major [M,D]
// BM=BN=128, BK=8, 256 threads, 8x8 per thread.
// ---------------------------------------------------------------------------
__global__ void __launch_bounds__(256) gemm_kernel(
    const float* __restrict__ A, const float* __restrict__ W,
    const float* __restrict__ bias, float* __restrict__ dst, int mode)
{
    __shared__ __align__(16) float As[8][132];
    __shared__ __align__(16) float Bs[8][132];

    const int tid  = threadIdx.x;
    const int m0   = blockIdx.x * 128;
    const int n0   = blockIdx.y * 128;
    const int lrow = tid >> 1;          // 0..127
    const int lk4  = (tid & 1) << 2;    // 0 or 4
    const int ty   = tid >> 4;          // 0..15
    const int tx   = tid & 15;          // 0..15

    const float* Ap = A + (size_t)(m0 + lrow) * D_M + lk4;
    const float* Wp = W + (size_t)(n0 + lrow) * D_M + lk4;

    float acc[8][8];
    #pragma unroll
    for (int i = 0; i < 8; i++)
        #pragma unroll
        for (int j = 0; j < 8; j++) acc[i][j] = 0.f;

    for (int k0 = 0; k0 < D_M; k0 += 8) {
        float4 av = *(const float4*)(Ap + k0);
        float4 wv = *(const float4*)(Wp + k0);
        As[lk4+0][lrow] = av.x; As[lk4+1][lrow] = av.y;
        As[lk4+2][lrow] = av.z; As[lk4+3][lrow] = av.w;
        Bs[lk4+0][lrow] = wv.x; Bs[lk4+1][lrow] = wv.y;
        Bs[lk4+2][lrow] = wv.z; Bs[lk4+3][lrow] = wv.w;
        __syncthreads();

        #pragma unroll
        for (int kk = 0; kk < 8; kk++) {
            float a[8], b[8];
            *(float4*)&a[0] = *(const float4*)&As[kk][ty*8];
            *(float4*)&a[4] = *(const float4*)&As[kk][ty*8+4];
            *(float4*)&b[0] = *(const float4*)&Bs[kk][tx*8];
            *(float4*)&b[4] = *(const float4*)&Bs[kk][tx*8+4];
            #pragma unroll
            for (int i = 0; i < 8; i++)
                #pragma unroll
                for (int j = 0; j < 8; j++)
                    acc[i][j] = fmaf(a[i], b[j], acc[i][j]);
        }
        __syncthreads();
    }

    #pragma unroll
    for (int i = 0; i < 8; i++) {
        const int m  = m0 + ty*8 + i;
        const int bb = m >> 11;      // / SEQ
        const int s  = m & 2047;
        #pragma unroll
        for (int j = 0; j < 8; j++) {
            const int n = n0 + tx*8 + j;
            const float v = acc[i][j] + bias[n];
            if (mode == 0) {
                const int h = n >> 6, d = n & 63;
                dst[(((size_t)(bb*NH + h))*SEQ + s)*HD + d] = v;
            } else {
                dst[(size_t)m * D_M + n] = v;
            }
        }
    }
}

// ---------------------------------------------------------------------------
// Flash attention, fp32, causal. One block = 64 queries of one (b,h).
// 256 threads. Online softmax. Only kt <= qt tiles computed.
// ---------------------------------------------------------------------------
#define LDK 65
#define LDV 68
#define LDP 68
#define ATTN_SMEM ((64*64 + 64*LDK + 64*LDV + 64*LDP + 3*64) * (int)sizeof(float))

__global__ void __launch_bounds__(256) attn_kernel()
{
    extern __shared__ float sm[];
    float* Qs   = sm;                 // [64][64]
    float* KsT  = Qs  + 64*64;        // [64][LDK]  KsT[d][j]
    float* Vs   = KsT + 64*LDK;       // [64][LDV]  Vs[k][d]
    float* Ps   = Vs  + 64*LDV;       // [64][LDP]  scores / probs
    float* mrow = Ps  + 64*LDP;       // [64]
    float* lrow = mrow + 64;          // [64]
    float* arow = lrow + 64;          // [64]

    const int tid  = threadIdx.x;
    const int qt   = blockIdx.x;      // 0..31
    const int h    = blockIdx.y;
    const int b    = blockIdx.z;
    const int q0   = qt * 64;
    const size_t base = ((size_t)(b*NH + h)) * SEQ * HD;

    const int ty = tid >> 4, tx = tid & 15;
    const int lane = tid & 31, warp = tid >> 5;

    // Load Q tile [64][64]
    #pragma unroll
    for (int it = 0; it < 4; it++) {
        int slot = tid + it*256;
        int r = slot >> 4;
        int c = (slot & 15) << 2;
        *(float4*)&Qs[r*HD + c] =
            *(const float4*)(g_q + base + (size_t)(q0 + r)*HD + c);
    }
    if (tid < 64) { mrow[tid] = -INFINITY; lrow[tid] = 0.f; }

    float acc[4][4];
    #pragma unroll
    for (int i = 0; i < 4; i++)
        #pragma unroll
        for (int j = 0; j < 4; j++) acc[i][j] = 0.f;

    __syncthreads();

    const float scale = 0.125f;  // 1/sqrt(64)

    for (int kt = 0; kt <= qt; kt++) {
        const int k0 = kt * 64;
        // Load K (transposed into KsT[d][j]) and V tiles
        #pragma unroll
        for (int it = 0; it < 4; it++) {
            int slot = tid + it*256;
            int r = slot >> 4;           // key index within tile
            int c = (slot & 15) << 2;    // dim offset
            float4 kv = *(const float4*)(g_k + base + (size_t)(k0 + r)*HD + c);
            KsT[(c+0)*LDK + r] = kv.x;
            KsT[(c+1)*LDK + r] = kv.y;
            KsT[(c+2)*LDK + r] = kv.z;
            KsT[(c+3)*LDK + r] = kv.w;
            *(float4*)&Vs[r*LDV + c] =
                *(const float4*)(g_v + base + (size_t)(k0 + r)*HD + c);
        }
        __syncthreads();

        // S = Q K^T  (4x4 per thread)
        float s[4][4];
        #pragma unroll
        for (int i = 0; i < 4; i++)
            #pragma unroll
            for (int j = 0; j < 4; j++) s[i][j] = 0.f;

        #pragma unroll 8
        for (int kd = 0; kd < HD; kd++) {
            float a[4], c[4];
            #pragma unroll
            for (int i = 0; i < 4; i++) a[i] = Qs[(ty*4+i)*HD + kd];
            #pragma unroll
            for (int j = 0; j < 4; j++) c[j] = KsT[kd*LDK + tx*4 + j];
            #pragma unroll
            for (int i = 0; i < 4; i++)
                #pragma unroll
                for (int j = 0; j < 4; j++)
                    s[i][j] = fmaf(a[i], c[j], s[i][j]);
        }

        const bool diag = (kt == qt);
        #pragma unroll
        for (int i = 0; i < 4; i++) {
            const int gi = ty*4 + i;
            #pragma unroll
            for (int j = 0; j < 4; j++) {
                const int gj = tx*4 + j;
                float v = s[i][j] * scale;
                if (diag && gj > gi) v = -INFINITY;
                Ps[gi*LDP + gj] = v;
            }
        }
        __syncthreads();

        // Online softmax: warp w handles rows 8w..8w+7, 2 cols per lane
        #pragma unroll
        for (int rr = 0; rr < 8; rr++) {
            const int r = warp*8 + rr;
            float s0 = Ps[r*LDP + lane];
            float s1 = Ps[r*LDP + lane + 32];
            float mx = fmaxf(s0, s1);
            #pragma unroll
            for (int o = 16; o > 0; o >>= 1)
                mx = fmaxf(mx, __shfl_xor_sync(0xffffffffu, mx, o));
            const float mprev = mrow[r];
            const float mnew  = fmaxf(mprev, mx);
            const float p0 = __expf(s0 - mnew);
            const float p1 = __expf(s1 - mnew);
            float sum = p0 + p1;
            #pragma unroll
            for (int o = 16; o > 0; o >>= 1)
                sum += __shfl_xor_sync(0xffffffffu, sum, o);
            Ps[r*LDP + lane]      = p0;
            Ps[r*LDP + lane + 32] = p1;
            if (lane == 0) {
                const float alpha = __expf(mprev - mnew);
                lrow[r] = lrow[r]*alpha + sum;
                mrow[r] = mnew;
                arow[r] = alpha;
            }
        }
        __syncthreads();

        // O = O*alpha + P @ V   (4x4 per thread over hd)
        float al[4];
        #pragma unroll
        for (int i = 0; i < 4; i++) al[i] = arow[ty*4 + i];
        #pragma unroll
        for (int i = 0; i < 4; i++)
            #pragma unroll
            for (int j = 0; j < 4; j++) acc[i][j] *= al[i];

        #pragma unroll 8
        for (int kk = 0; kk < 64; kk++) {
            float p[4], vv[4];
            #pragma unroll
            for (int i = 0; i < 4; i++) p[i] = Ps[(ty*4+i)*LDP + kk];
            #pragma unroll
            for (int j = 0; j < 4; j++) vv[j] = Vs[kk*LDV + tx*4 + j];
            #pragma unroll
            for (int i = 0; i < 4; i++)
                #pragma unroll
                for (int j = 0; j < 4; j++)
                    acc[i][j] = fmaf(p[i], vv[j], acc[i][j]);
        }
        __syncthreads();
    }

    // Normalize and write to g_y [B,S,D]
    float linv[4];
    #pragma unroll
    for (int i = 0; i < 4; i++) linv[i] = 1.0f / lrow[ty*4 + i];
    #pragma unroll
    for (int i = 0; i < 4; i++) {
        const int s_idx = q0 + ty*4 + i;
        #pragma unroll
        for (int j = 0; j < 4; j++) {
            g_y[((size_t)(b*SEQ + s_idx))*D_M + h*HD + tx*4 + j] = acc[i][j] * linv[i];
        }
    }
}

// ---------------------------------------------------------------------------
extern "C" void kernel_launch(void* const* d_in, const int* in_sizes, int n_in,
                              void* d_out, int out_size)
{
    const float* x  = (const float*)d_in[0];
    const float* Wq = (const float*)d_in[1];
    const float* bq = (const float*)d_in[2];
    const float* Wk = (const float*)d_in[3];
    const float* bk = (const float*)d_in[4];
    const float* Wv = (const float*)d_in[5];
    const float* bv = (const float*)d_in[6];
    const float* Wo = (const float*)d_in[7];
    const float* bo = (const float*)d_in[8];
    float* out = (float*)d_out;

    float *qp, *kp, *vp, *yp;
    cudaGetSymbolAddress((void**)&qp, g_q);
    cudaGetSymbolAddress((void**)&kp, g_k);
    cudaGetSymbolAddress((void**)&vp, g_v);
    cudaGetSymbolAddress((void**)&yp, g_y);

    dim3 gg(MTOT/128, D_M/128);
    gemm_kernel<<<gg, 256>>>(x, Wq, bq, qp, 0);
    gemm_kernel<<<gg, 256>>>(x, Wk, bk, kp, 0);
    gemm_kernel<<<gg, 256>>>(x, Wv, bv, vp, 0);

    cudaFuncSetAttribute(attn_kernel,
                         cudaFuncAttributeMaxDynamicSharedMemorySize, ATTN_SMEM);
    attn_kernel<<<dim3(SEQ/64, NH, BATCH), 256, ATTN_SMEM>>>();

    gemm_kernel<<<gg, 256>>>(yp, Wo, bo, out, 1);
}

// round 3
// speedup vs baseline: 1.5042x; 1.5042x over previous
#include <cuda_runtime.h>
#include <cuda_bf16.h>
#include <math.h>
#include <stdint.h>

#define D_M   1024
#define NH    16
#define HD    64
#define BATCH 4
#define SEQ   2048
#define MTOT  (BATCH*SEQ)

// ---------------- device scratch (no allocation allowed) -------------------
__device__ float g_q[(size_t)BATCH*NH*SEQ*HD];   // [B,H,S,hd] fp32
__device__ float g_k[(size_t)BATCH*NH*SEQ*HD];
__device__ float g_v[(size_t)BATCH*NH*SEQ*HD];
__device__ float g_y[(size_t)MTOT*D_M];          // [B,S,D] attention output fp32

__device__ __nv_bfloat16 g_xhi[(size_t)MTOT*D_M];
__device__ __nv_bfloat16 g_xlo[(size_t)MTOT*D_M];
__device__ __nv_bfloat16 g_yhi[(size_t)MTOT*D_M];
__device__ __nv_bfloat16 g_ylo[(size_t)MTOT*D_M];
__device__ __nv_bfloat16 g_wh[4][(size_t)D_M*D_M];
__device__ __nv_bfloat16 g_wl[4][(size_t)D_M*D_M];

// ---------------- helpers ----------------------------------------------------
__device__ __forceinline__ uint32_t smem_u32(const void* p) {
    uint32_t a;
    asm("{ .reg .u64 t; cvta.to.shared.u64 t, %1; cvt.u32.u64 %0, t; }"
        : "=r"(a) : "l"(p));
    return a;
}
__device__ __forceinline__ void cp16(uint32_t s, const void* g) {
    asm volatile("cp.async.cg.shared.global [%0], [%1], 16;"
                 :: "r"(s), "l"(g) : "memory");
}
#define CP_COMMIT() asm volatile("cp.async.commit_group;" ::: "memory")
#define CP_WAIT1()  asm volatile("cp.async.wait_group 1;" ::: "memory")

__device__ __forceinline__ void ldsm4(uint32_t* r, uint32_t addr) {
    asm volatile("ldmatrix.sync.aligned.m8n8.x4.shared.b16 {%0,%1,%2,%3}, [%4];"
                 : "=r"(r[0]), "=r"(r[1]), "=r"(r[2]), "=r"(r[3]) : "r"(addr));
}
__device__ __forceinline__ void mma16816(float* c, const uint32_t* a,
                                         uint32_t b0, uint32_t b1) {
    asm volatile(
        "mma.sync.aligned.m16n8k16.row.col.f32.bf16.bf16.f32 "
        "{%0,%1,%2,%3}, {%4,%5,%6,%7}, {%8,%9}, {%0,%1,%2,%3};"
        : "+f"(c[0]), "+f"(c[1]), "+f"(c[2]), "+f"(c[3])
        : "r"(a[0]), "r"(a[1]), "r"(a[2]), "r"(a[3]), "r"(b0), "r"(b1));
}

// ---------------- fp32 -> bf16 hi/lo split ----------------------------------
__global__ void __launch_bounds__(256) split_kernel(
    const float* __restrict__ src, __nv_bfloat16* __restrict__ hi,
    __nv_bfloat16* __restrict__ lo, int n4)
{
    int i = blockIdx.x * 256 + threadIdx.x;
    if (i >= n4) return;
    float4 v = ((const float4*)src)[i];
    __nv_bfloat16 h0 = __float2bfloat16_rn(v.x);
    __nv_bfloat16 h1 = __float2bfloat16_rn(v.y);
    __nv_bfloat16 h2 = __float2bfloat16_rn(v.z);
    __nv_bfloat16 h3 = __float2bfloat16_rn(v.w);
    __nv_bfloat16 l0 = __float2bfloat16_rn(v.x - __bfloat162float(h0));
    __nv_bfloat16 l1 = __float2bfloat16_rn(v.y - __bfloat162float(h1));
    __nv_bfloat16 l2 = __float2bfloat16_rn(v.z - __bfloat162float(h2));
    __nv_bfloat16 l3 = __float2bfloat16_rn(v.w - __bfloat162float(h3));
    ((__nv_bfloat162*)hi)[2*i]   = __halves2bfloat162(h0, h1);
    ((__nv_bfloat162*)hi)[2*i+1] = __halves2bfloat162(h2, h3);
    ((__nv_bfloat162*)lo)[2*i]   = __halves2bfloat162(l0, l1);
    ((__nv_bfloat162*)lo)[2*i+1] = __halves2bfloat162(l2, l3);
}

// ---------------- mma.sync bf16x3 GEMM ---------------------------------------
// out[m,n] = sum_k A[m,k]*W[n,k] + bias[n]   (A:[M,1024], W:[1024,1024], K-major)
// mode 0: scatter into [B,H,S,hd] (QKV);  mode 1: row-major [M,D]
#define BKG     32
#define LDT     40                         // bf16 per smem row (80 B, conflict-free)
#define TILE_B  (128*LDT*2)                // 10240 B per tile
#define STAGE_B (4*TILE_B)                 // Ahi, Alo, Whi, Wlo
#define NSTAGE  3
#define SMEM_GEMM (NSTAGE*STAGE_B)

__global__ void __launch_bounds__(256, 1) gemm_mma(
    const __nv_bfloat16* __restrict__ Ahi, const __nv_bfloat16* __restrict__ Alo,
    const __nv_bfloat16* __restrict__ Whi, const __nv_bfloat16* __restrict__ Wlo,
    const float* __restrict__ bias, float* __restrict__ dst, int mode)
{
    extern __shared__ __align__(128) char smem[];
    const int tid  = threadIdx.x;
    const int warp = tid >> 5, lane = tid & 31;
    const int m0 = blockIdx.x * 128, n0 = blockIdx.y * 128;
    const int wm = warp >> 2, wn = warp & 3;        // 2 x 4 warp grid
    const uint32_t sb = smem_u32(smem);

    // per-thread cp.async descriptors (8 x 16B chunks per stage)
    uint32_t soff[8]; const __nv_bfloat16* gsrc[8];
    #pragma unroll
    for (int i = 0; i < 8; i++) {
        int id = tid + i * 256;              // 0..2047
        int tile = id >> 9, idx = id & 511, row = idx >> 2, c = idx & 3;
        soff[i] = (uint32_t)(tile * TILE_B + row * (LDT*2) + c * 16);
        const __nv_bfloat16* bp = (tile == 0) ? Ahi : (tile == 1) ? Alo
                                 : (tile == 2) ? Whi : Wlo;
        gsrc[i] = bp + (size_t)((tile < 2 ? m0 : n0) + row) * D_M + c * 8;
    }

    float acc[4][4][4];
    #pragma unroll
    for (int mi = 0; mi < 4; mi++)
        #pragma unroll
        for (int ni = 0; ni < 4; ni++)
            #pragma unroll
            for (int r = 0; r < 4; r++) acc[mi][ni][r] = 0.f;

    // ldmatrix address components
    const int a_row  = wm * 64 + (lane & 15);
    const int a_col8 = (lane >> 4);                  // 0/1 (k half)
    const int bg = lane >> 3, b_in = lane & 7;
    const int b_row  = wn * 32 + (bg >> 1) * 8 + b_in;
    const int b_k8   = bg & 1;

    // prologue: stages 0,1
    #pragma unroll
    for (int p = 0; p < 2; p++) {
        #pragma unroll
        for (int i = 0; i < 8; i++)
            cp16(sb + p * STAGE_B + soff[i], gsrc[i] + p * BKG);
        CP_COMMIT();
    }

    for (int kt = 0; kt < 32; kt++) {
        CP_WAIT1();
        __syncthreads();

        const uint32_t stg = sb + (kt % 3) * STAGE_B;
        #pragma unroll
        for (int kk = 0; kk < 2; kk++) {
            const uint32_t acol = (uint32_t)((kk * 16 + a_col8 * 8) * 2);
            const uint32_t bcol = (uint32_t)((kk * 16 + b_k8 * 8) * 2);
            uint32_t ah[4][4], al[4][4], wh_[2][4], wl_[2][4];
            #pragma unroll
            for (int mi = 0; mi < 4; mi++)
                ldsm4(ah[mi], stg + (a_row + mi*16) * (LDT*2) + acol);
            #pragma unroll
            for (int pi = 0; pi < 2; pi++)
                ldsm4(wh_[pi], stg + 2*TILE_B + (b_row + pi*16) * (LDT*2) + bcol);
            #pragma unroll
            for (int mi = 0; mi < 4; mi++)
                #pragma unroll
                for (int ni = 0; ni < 4; ni++)
                    mma16816(acc[mi][ni], ah[mi],
                             wh_[ni>>1][(ni&1)*2], wh_[ni>>1][(ni&1)*2+1]);
            #pragma unroll
            for (int mi = 0; mi < 4; mi++)
                ldsm4(al[mi], stg + TILE_B + (a_row + mi*16) * (LDT*2) + acol);
            #pragma unroll
            for (int mi = 0; mi < 4; mi++)
                #pragma unroll
                for (int ni = 0; ni < 4; ni++)
                    mma16816(acc[mi][ni], al[mi],
                             wh_[ni>>1][(ni&1)*2], wh_[ni>>1][(ni&1)*2+1]);
            #pragma unroll
            for (int pi = 0; pi < 2; pi++)
                ldsm4(wl_[pi], stg + 3*TILE_B + (b_row + pi*16) * (LDT*2) + bcol);
            #pragma unroll
            for (int mi = 0; mi < 4; mi++)
                #pragma unroll
                for (int ni = 0; ni < 4; ni++)
                    mma16816(acc[mi][ni], ah[mi],
                             wl_[ni>>1][(ni&1)*2], wl_[ni>>1][(ni&1)*2+1]);
        }
        __syncthreads();

        if (kt < 30) {
            const int knext = kt + 2;
            const uint32_t dstg = sb + (knext % 3) * STAGE_B;
            #pragma unroll
            for (int i = 0; i < 8; i++)
                cp16(dstg + soff[i], gsrc[i] + knext * BKG);
        }
        CP_COMMIT();
    }

    // epilogue: registers -> global with bias (+ optional head scatter)
    #pragma unroll
    for (int mi = 0; mi < 4; mi++) {
        #pragma unroll
        for (int ni = 0; ni < 4; ni++) {
            const int m_a = m0 + wm*64 + mi*16 + (lane >> 2);
            const int n_a = n0 + wn*32 + ni*8 + (lane & 3)*2;
            const float b0 = bias[n_a], b1 = bias[n_a + 1];
            float2 v0 = make_float2(acc[mi][ni][0] + b0, acc[mi][ni][1] + b1);
            float2 v1 = make_float2(acc[mi][ni][2] + b0, acc[mi][ni][3] + b1);
            if (mode == 0) {
                const int h = n_a >> 6, d = n_a & 63;
                const int b  = m_a >> 11, s  = m_a & 2047;
                const int b2 = (m_a+8) >> 11, s2 = (m_a+8) & 2047;
                *(float2*)&dst[(((size_t)(b *NH + h))*SEQ + s )*HD + d] = v0;
                *(float2*)&dst[(((size_t)(b2*NH + h))*SEQ + s2)*HD + d] = v1;
            } else {
                *(float2*)&dst[(size_t)m_a     * D_M + n_a] = v0;
                *(float2*)&dst[(size_t)(m_a+8) * D_M + n_a] = v1;
            }
        }
    }
}

// ---------------- flash attention (fp32 SIMT, unchanged) --------------------
#define LDK 65
#define LDV 68
#define LDP 68
#define ATTN_SMEM ((64*64 + 64*LDK + 64*LDV + 64*LDP + 3*64) * (int)sizeof(float))

__global__ void __launch_bounds__(256) attn_kernel()
{
    extern __shared__ float sm[];
    float* Qs   = sm;
    float* KsT  = Qs  + 64*64;
    float* Vs   = KsT + 64*LDK;
    float* Ps   = Vs  + 64*LDV;
    float* mrow = Ps  + 64*LDP;
    float* lrow = mrow + 64;
    float* arow = lrow + 64;

    const int tid  = threadIdx.x;
    const int qt   = blockIdx.x;
    const int h    = blockIdx.y;
    const int b    = blockIdx.z;
    const int q0   = qt * 64;
    const size_t base = ((size_t)(b*NH + h)) * SEQ * HD;

    const int ty = tid >> 4, tx = tid & 15;
    const int lane = tid & 31, warp = tid >> 5;

    #pragma unroll
    for (int it = 0; it < 4; it++) {
        int slot = tid + it*256;
        int r = slot >> 4;
        int c = (slot & 15) << 2;
        *(float4*)&Qs[r*HD + c] =
            *(const float4*)(g_q + base + (size_t)(q0 + r)*HD + c);
    }
    if (tid < 64) { mrow[tid] = -INFINITY; lrow[tid] = 0.f; }

    float acc[4][4];
    #pragma unroll
    for (int i = 0; i < 4; i++)
        #pragma unroll
        for (int j = 0; j < 4; j++) acc[i][j] = 0.f;

    __syncthreads();

    const float scale = 0.125f;

    for (int kt = 0; kt <= qt; kt++) {
        const int k0 = kt * 64;
        #pragma unroll
        for (int it = 0; it < 4; it++) {
            int slot = tid + it*256;
            int r = slot >> 4;
            int c = (slot & 15) << 2;
            float4 kv = *(const float4*)(g_k + base + (size_t)(k0 + r)*HD + c);
            KsT[(c+0)*LDK + r] = kv.x;
            KsT[(c+1)*LDK + r] = kv.y;
            KsT[(c+2)*LDK + r] = kv.z;
            KsT[(c+3)*LDK + r] = kv.w;
            *(float4*)&Vs[r*LDV + c] =
                *(const float4*)(g_v + base + (size_t)(k0 + r)*HD + c);
        }
        __syncthreads();

        float s[4][4];
        #pragma unroll
        for (int i = 0; i < 4; i++)
            #pragma unroll
            for (int j = 0; j < 4; j++) s[i][j] = 0.f;

        #pragma unroll 8
        for (int kd = 0; kd < HD; kd++) {
            float a[4], c[4];
            #pragma unroll
            for (int i = 0; i < 4; i++) a[i] = Qs[(ty*4+i)*HD + kd];
            #pragma unroll
            for (int j = 0; j < 4; j++) c[j] = KsT[kd*LDK + tx*4 + j];
            #pragma unroll
            for (int i = 0; i < 4; i++)
                #pragma unroll
                for (int j = 0; j < 4; j++)
                    s[i][j] = fmaf(a[i], c[j], s[i][j]);
        }

        const bool diag = (kt == qt);
        #pragma unroll
        for (int i = 0; i < 4; i++) {
            const int gi = ty*4 + i;
            #pragma unroll
            for (int j = 0; j < 4; j++) {
                const int gj = tx*4 + j;
                float v = s[i][j] * scale;
                if (diag && gj > gi) v = -INFINITY;
                Ps[gi*LDP + gj] = v;
            }
        }
        __syncthreads();

        #pragma unroll
        for (int rr = 0; rr < 8; rr++) {
            const int r = warp*8 + rr;
            float s0 = Ps[r*LDP + lane];
            float s1 = Ps[r*LDP + lane + 32];
            float mx = fmaxf(s0, s1);
            #pragma unroll
            for (int o = 16; o > 0; o >>= 1)
                mx = fmaxf(mx, __shfl_xor_sync(0xffffffffu, mx, o));
            const float mprev = mrow[r];
            const float mnew  = fmaxf(mprev, mx);
            const float p0 = __expf(s0 - mnew);
            const float p1 = __expf(s1 - mnew);
            float sum = p0 + p1;
            #pragma unroll
            for (int o = 16; o > 0; o >>= 1)
                sum += __shfl_xor_sync(0xffffffffu, sum, o);
            Ps[r*LDP + lane]      = p0;
            Ps[r*LDP + lane + 32] = p1;
            if (lane == 0) {
                const float alpha = __expf(mprev - mnew);
                lrow[r] = lrow[r]*alpha + sum;
                mrow[r] = mnew;
                arow[r] = alpha;
            }
        }
        __syncthreads();

        float al[4];
        #pragma unroll
        for (int i = 0; i < 4; i++) al[i] = arow[ty*4 + i];
        #pragma unroll
        for (int i = 0; i < 4; i++)
            #pragma unroll
            for (int j = 0; j < 4; j++) acc[i][j] *= al[i];

        #pragma unroll 8
        for (int kk = 0; kk < 64; kk++) {
            float p[4], vv[4];
            #pragma unroll
            for (int i = 0; i < 4; i++) p[i] = Ps[(ty*4+i)*LDP + kk];
            #pragma unroll
            for (int j = 0; j < 4; j++) vv[j] = Vs[kk*LDV + tx*4 + j];
            #pragma unroll
            for (int i = 0; i < 4; i++)
                #pragma unroll
                for (int j = 0; j < 4; j++)
                    acc[i][j] = fmaf(p[i], vv[j], acc[i][j]);
        }
        __syncthreads();
    }

    float linv[4];
    #pragma unroll
    for (int i = 0; i < 4; i++) linv[i] = 1.0f / lrow[ty*4 + i];
    #pragma unroll
    for (int i = 0; i < 4; i++) {
        const int s_idx = q0 + ty*4 + i;
        #pragma unroll
        for (int j = 0; j < 4; j++) {
            g_y[((size_t)(b*SEQ + s_idx))*D_M + h*HD + tx*4 + j] = acc[i][j] * linv[i];
        }
    }
}

// ---------------------------------------------------------------------------
extern "C" void kernel_launch(void* const* d_in, const int* in_sizes, int n_in,
                              void* d_out, int out_size)
{
    const float* x  = (const float*)d_in[0];
    const float* Wq = (const float*)d_in[1];
    const float* bq = (const float*)d_in[2];
    const float* Wk = (const float*)d_in[3];
    const float* bk = (const float*)d_in[4];
    const float* Wv = (const float*)d_in[5];
    const float* bv = (const float*)d_in[6];
    const float* Wo = (const float*)d_in[7];
    const float* bo = (const float*)d_in[8];
    float* out = (float*)d_out;

    float *qp, *kp, *vp, *yp;
    cudaGetSymbolAddress((void**)&qp, g_q);
    cudaGetSymbolAddress((void**)&kp, g_k);
    cudaGetSymbolAddress((void**)&vp, g_v);
    cudaGetSymbolAddress((void**)&yp, g_y);
    __nv_bfloat16 *xhi, *xlo, *yhi, *ylo, *wh, *wl;
    cudaGetSymbolAddress((void**)&xhi, g_xhi);
    cudaGetSymbolAddress((void**)&xlo, g_xlo);
    cudaGetSymbolAddress((void**)&yhi, g_yhi);
    cudaGetSymbolAddress((void**)&ylo, g_ylo);
    cudaGetSymbolAddress((void**)&wh, g_wh);
    cudaGetSymbolAddress((void**)&wl, g_wl);
    const size_t WSZ = (size_t)D_M * D_M;

    const int n4x = MTOT * D_M / 4;
    const int n4w = D_M * D_M / 4;
    split_kernel<<<n4x/256, 256>>>(x,  xhi, xlo, n4x);
    split_kernel<<<n4w/256, 256>>>(Wq, wh + 0*WSZ, wl + 0*WSZ, n4w);
    split_kernel<<<n4w/256, 256>>>(Wk, wh + 1*WSZ, wl + 1*WSZ, n4w);
    split_kernel<<<n4w/256, 256>>>(Wv, wh + 2*WSZ, wl + 2*WSZ, n4w);
    split_kernel<<<n4w/256, 256>>>(Wo, wh + 3*WSZ, wl + 3*WSZ, n4w);

    cudaFuncSetAttribute(gemm_mma,
                         cudaFuncAttributeMaxDynamicSharedMemorySize, SMEM_GEMM);
    cudaFuncSetAttribute(attn_kernel,
                         cudaFuncAttributeMaxDynamicSharedMemorySize, ATTN_SMEM);

    dim3 gg(MTOT/128, D_M/128);
    gemm_mma<<<gg, 256, SMEM_GEMM>>>(xhi, xlo, wh + 0*WSZ, wl + 0*WSZ, bq, qp, 0);
    gemm_mma<<<gg, 256, SMEM_GEMM>>>(xhi, xlo, wh + 1*WSZ, wl + 1*WSZ, bk, kp, 0);
    gemm_mma<<<gg, 256, SMEM_GEMM>>>(xhi, xlo, wh + 2*WSZ, wl + 2*WSZ, bv, vp, 0);

    attn_kernel<<<dim3(SEQ/64, NH, BATCH), 256, ATTN_SMEM>>>();

    split_kernel<<<n4x/256, 256>>>(yp, yhi, ylo, n4x);
    gemm_mma<<<gg, 256, SMEM_GEMM>>>(yhi, ylo, wh + 3*WSZ, wl + 3*WSZ, bo, out, 1);
}

// round 4
// speedup vs baseline: 2.5874x; 1.7201x over previous
#include <cuda_runtime.h>
#include <cuda_bf16.h>
#include <math.h>
#include <stdint.h>

#define D_M   1024
#define NH    16
#define HD    64
#define BATCH 4
#define SEQ   2048
#define MTOT  (BATCH*SEQ)

// ---------------- device scratch (no allocation allowed) -------------------
__device__ __nv_bfloat16 g_qh[(size_t)BATCH*NH*SEQ*HD];
__device__ __nv_bfloat16 g_ql[(size_t)BATCH*NH*SEQ*HD];
__device__ __nv_bfloat16 g_kh[(size_t)BATCH*NH*SEQ*HD];
__device__ __nv_bfloat16 g_kl[(size_t)BATCH*NH*SEQ*HD];
__device__ __nv_bfloat16 g_vh[(size_t)BATCH*NH*SEQ*HD];
__device__ __nv_bfloat16 g_vl[(size_t)BATCH*NH*SEQ*HD];
__device__ __nv_bfloat16 g_xhi[(size_t)MTOT*D_M];
__device__ __nv_bfloat16 g_xlo[(size_t)MTOT*D_M];
__device__ __nv_bfloat16 g_yhi[(size_t)MTOT*D_M];
__device__ __nv_bfloat16 g_ylo[(size_t)MTOT*D_M];
__device__ __nv_bfloat16 g_wh[4][(size_t)D_M*D_M];
__device__ __nv_bfloat16 g_wl[4][(size_t)D_M*D_M];

// ---------------- helpers ----------------------------------------------------
__device__ __forceinline__ uint32_t smem_u32(const void* p) {
    uint32_t a;
    asm("{ .reg .u64 t; cvta.to.shared.u64 t, %1; cvt.u32.u64 %0, t; }"
        : "=r"(a) : "l"(p));
    return a;
}
__device__ __forceinline__ void cp16(uint32_t s, const void* g) {
    asm volatile("cp.async.cg.shared.global [%0], [%1], 16;"
                 :: "r"(s), "l"(g) : "memory");
}
#define CP_COMMIT() asm volatile("cp.async.commit_group;" ::: "memory")
#define CP_WAIT1()  asm volatile("cp.async.wait_group 1;" ::: "memory")
#define CP_WAIT0()  asm volatile("cp.async.wait_group 0;" ::: "memory")

__device__ __forceinline__ void ldsm4(uint32_t* r, uint32_t addr) {
    asm volatile("ldmatrix.sync.aligned.m8n8.x4.shared.b16 {%0,%1,%2,%3}, [%4];"
                 : "=r"(r[0]), "=r"(r[1]), "=r"(r[2]), "=r"(r[3]) : "r"(addr));
}
__device__ __forceinline__ void ldsm4t(uint32_t* r, uint32_t addr) {
    asm volatile("ldmatrix.sync.aligned.m8n8.x4.trans.shared.b16 {%0,%1,%2,%3}, [%4];"
                 : "=r"(r[0]), "=r"(r[1]), "=r"(r[2]), "=r"(r[3]) : "r"(addr));
}
__device__ __forceinline__ void mma16816(float* c, const uint32_t* a,
                                         uint32_t b0, uint32_t b1) {
    asm volatile(
        "mma.sync.aligned.m16n8k16.row.col.f32.bf16.bf16.f32 "
        "{%0,%1,%2,%3}, {%4,%5,%6,%7}, {%8,%9}, {%0,%1,%2,%3};"
        : "+f"(c[0]), "+f"(c[1]), "+f"(c[2]), "+f"(c[3])
        : "r"(a[0]), "r"(a[1]), "r"(a[2]), "r"(a[3]), "r"(b0), "r"(b1));
}
// fast exp2 on FMA pipe (deg-5 poly, rel err ~2.4e-6), t <= 0
__device__ __forceinline__ float fexp2(float t) {
    t = fmaxf(t, -126.0f);
    float z  = t + 12582912.0f;          // round-to-int magic
    int   n  = __float_as_int(z);
    float fn = z - 12582912.0f;
    float f  = t - fn;                   // f in [-0.5, 0.5]
    float p  =       1.3333558146e-3f;
    p = fmaf(p, f,   9.6181291076e-3f);
    p = fmaf(p, f,   5.5504108664e-2f);
    p = fmaf(p, f,   2.4022650696e-1f);
    p = fmaf(p, f,   6.9314718056e-1f);
    p = fmaf(p, f,   1.0f);
    return __int_as_float(__float_as_int(p) + (n << 23));
}
// split two floats into packed bf16x2 hi/lo
__device__ __forceinline__ void psplit(float a, float b, uint32_t& hi, uint32_t& lo) {
    __nv_bfloat16 ha = __float2bfloat16_rn(a), hb = __float2bfloat16_rn(b);
    __nv_bfloat16 la = __float2bfloat16_rn(a - __bfloat162float(ha));
    __nv_bfloat16 lb = __float2bfloat16_rn(b - __bfloat162float(hb));
    __nv_bfloat162 H = __halves2bfloat162(ha, hb), L = __halves2bfloat162(la, lb);
    hi = *(uint32_t*)&H; lo = *(uint32_t*)&L;
}

// ---------------- fp32 -> bf16 hi/lo split ----------------------------------
__global__ void __launch_bounds__(256) split_kernel(
    const float* __restrict__ src, __nv_bfloat16* __restrict__ hi,
    __nv_bfloat16* __restrict__ lo, int n4)
{
    int i = blockIdx.x * 256 + threadIdx.x;
    if (i >= n4) return;
    float4 v = ((const float4*)src)[i];
    uint32_t h0, l0, h1, l1;
    psplit(v.x, v.y, h0, l0);
    psplit(v.z, v.w, h1, l1);
    ((uint32_t*)hi)[2*i]   = h0; ((uint32_t*)hi)[2*i+1] = h1;
    ((uint32_t*)lo)[2*i]   = l0; ((uint32_t*)lo)[2*i+1] = l1;
}

// ---------------- mma.sync bf16x3 GEMM ---------------------------------------
// out[m,n] = (sum_k A[m,k]*W[n,k] + bias[n]) * outscale
// mode 0: split to bf16 hi/lo, scatter into [B,H,S,hd]; mode 1: fp32 [M,D]
#define BKG     32
#define LDT     40
#define TILE_B  (128*LDT*2)
#define STAGE_B (4*TILE_B)
#define SMEM_GEMM (3*STAGE_B)

__global__ void __launch_bounds__(256, 1) gemm_mma(
    const __nv_bfloat16* __restrict__ Ahi, const __nv_bfloat16* __restrict__ Alo,
    const __nv_bfloat16* __restrict__ Whi, const __nv_bfloat16* __restrict__ Wlo,
    const float* __restrict__ bias,
    __nv_bfloat16* __restrict__ dsth, __nv_bfloat16* __restrict__ dstl,
    float* __restrict__ fdst, int mode, float outscale)
{
    extern __shared__ __align__(128) char smem[];
    const int tid  = threadIdx.x;
    const int warp = tid >> 5, lane = tid & 31;
    const int m0 = blockIdx.x * 128, n0 = blockIdx.y * 128;
    const int wm = warp >> 2, wn = warp & 3;
    const uint32_t sb = smem_u32(smem);

    uint32_t soff[8]; const __nv_bfloat16* gsrc[8];
    #pragma unroll
    for (int i = 0; i < 8; i++) {
        int id = tid + i * 256;
        int tile = id >> 9, idx = id & 511, row = idx >> 2, c = idx & 3;
        soff[i] = (uint32_t)(tile * TILE_B + row * (LDT*2) + c * 16);
        const __nv_bfloat16* bp = (tile == 0) ? Ahi : (tile == 1) ? Alo
                                 : (tile == 2) ? Whi : Wlo;
        gsrc[i] = bp + (size_t)((tile < 2 ? m0 : n0) + row) * D_M + c * 8;
    }

    float acc[4][4][4];
    #pragma unroll
    for (int mi = 0; mi < 4; mi++)
        #pragma unroll
        for (int ni = 0; ni < 4; ni++)
            #pragma unroll
            for (int r = 0; r < 4; r++) acc[mi][ni][r] = 0.f;

    const int a_row  = wm * 64 + (lane & 15);
    const int a_col8 = (lane >> 4);
    const int bg = lane >> 3, b_in = lane & 7;
    const int b_row  = wn * 32 + (bg >> 1) * 8 + b_in;
    const int b_k8   = bg & 1;

    #pragma unroll
    for (int p = 0; p < 2; p++) {
        #pragma unroll
        for (int i = 0; i < 8; i++)
            cp16(sb + p * STAGE_B + soff[i], gsrc[i] + p * BKG);
        CP_COMMIT();
    }

    for (int kt = 0; kt < 32; kt++) {
        CP_WAIT1();
        __syncthreads();

        const uint32_t stg = sb + (kt % 3) * STAGE_B;
        #pragma unroll
        for (int kk = 0; kk < 2; kk++) {
            const uint32_t acol = (uint32_t)((kk * 16 + a_col8 * 8) * 2);
            const uint32_t bcol = (uint32_t)((kk * 16 + b_k8 * 8) * 2);
            uint32_t ah[4][4], al[4][4], wh_[2][4], wl_[2][4];
            #pragma unroll
            for (int mi = 0; mi < 4; mi++)
                ldsm4(ah[mi], stg + (a_row + mi*16) * (LDT*2) + acol);
            #pragma unroll
            for (int pi = 0; pi < 2; pi++)
                ldsm4(wh_[pi], stg + 2*TILE_B + (b_row + pi*16) * (LDT*2) + bcol);
            #pragma unroll
            for (int mi = 0; mi < 4; mi++)
                #pragma unroll
                for (int ni = 0; ni < 4; ni++)
                    mma16816(acc[mi][ni], ah[mi],
                             wh_[ni>>1][(ni&1)*2], wh_[ni>>1][(ni&1)*2+1]);
            #pragma unroll
            for (int mi = 0; mi < 4; mi++)
                ldsm4(al[mi], stg + TILE_B + (a_row + mi*16) * (LDT*2) + acol);
            #pragma unroll
            for (int mi = 0; mi < 4; mi++)
                #pragma unroll
                for (int ni = 0; ni < 4; ni++)
                    mma16816(acc[mi][ni], al[mi],
                             wh_[ni>>1][(ni&1)*2], wh_[ni>>1][(ni&1)*2+1]);
            #pragma unroll
            for (int pi = 0; pi < 2; pi++)
                ldsm4(wl_[pi], stg + 3*TILE_B + (b_row + pi*16) * (LDT*2) + bcol);
            #pragma unroll
            for (int mi = 0; mi < 4; mi++)
                #pragma unroll
                for (int ni = 0; ni < 4; ni++)
                    mma16816(acc[mi][ni], ah[mi],
                             wl_[ni>>1][(ni&1)*2], wl_[ni>>1][(ni&1)*2+1]);
        }
        __syncthreads();

        if (kt < 30) {
            const int knext = kt + 2;
            const uint32_t dstg = sb + (knext % 3) * STAGE_B;
            #pragma unroll
            for (int i = 0; i < 8; i++)
                cp16(dstg + soff[i], gsrc[i] + knext * BKG);
        }
        CP_COMMIT();
    }

    #pragma unroll
    for (int mi = 0; mi < 4; mi++) {
        #pragma unroll
        for (int ni = 0; ni < 4; ni++) {
            const int m_a = m0 + wm*64 + mi*16 + (lane >> 2);
            const int n_a = n0 + wn*32 + ni*8 + (lane & 3)*2;
            const float b0 = bias[n_a], b1 = bias[n_a + 1];
            const float v00 = (acc[mi][ni][0] + b0) * outscale;
            const float v01 = (acc[mi][ni][1] + b1) * outscale;
            const float v10 = (acc[mi][ni][2] + b0) * outscale;
            const float v11 = (acc[mi][ni][3] + b1) * outscale;
            if (mode == 0) {
                const int h = n_a >> 6, d = n_a & 63;
                const int b  = m_a >> 11, s  = m_a & 2047;
                const int b2 = (m_a+8) >> 11, s2 = (m_a+8) & 2047;
                const size_t i0 = (((size_t)(b *NH + h))*SEQ + s )*HD + d;
                const size_t i1 = (((size_t)(b2*NH + h))*SEQ + s2)*HD + d;
                uint32_t hi, lo;
                psplit(v00, v01, hi, lo);
                *(uint32_t*)(dsth + i0) = hi; *(uint32_t*)(dstl + i0) = lo;
                psplit(v10, v11, hi, lo);
                *(uint32_t*)(dsth + i1) = hi; *(uint32_t*)(dstl + i1) = lo;
            } else {
                *(float2*)&fdst[(size_t)m_a     * D_M + n_a] = make_float2(v00, v01);
                *(float2*)&fdst[(size_t)(m_a+8) * D_M + n_a] = make_float2(v10, v11);
            }
        }
    }
}

// ---------------- flash attention, bf16x3 mma.sync --------------------------
// CTA: 128 q rows of one (b,h); 8 warps x 16 rows; 64-key tiles, causal skip.
#define ALDB 144                       // 72 bf16 row stride (bytes)
#define SM_Q    0
#define SM_QL   (128*ALDB)             // 18432
#define SM_KV   (2*128*ALDB)           // 36864
#define STG_SZ  (4*64*ALDB)            // 36864 (Kh,Kl,Vh,Vl)
#define AKH     0
#define AKL     (64*ALDB)
#define AVH     (2*64*ALDB)
#define AVL     (3*64*ALDB)
#define ATTN_SMEM (SM_KV + 2*STG_SZ)   // 110592

__device__ __forceinline__ void load_kv_tile(uint32_t dst, size_t gbase,
                                             int k0, int tid)
{
    #pragma unroll
    for (int i = 0; i < 2; i++) {
        int c = tid + i * 256;            // 0..511
        int r = c >> 3, c16 = c & 7;
        const size_t go = gbase + (size_t)(k0 + r) * HD + c16 * 8;
        const uint32_t so = (uint32_t)(r * ALDB + c16 * 16);
        cp16(dst + AKH + so, g_kh + go);
        cp16(dst + AKL + so, g_kl + go);
        cp16(dst + AVH + so, g_vh + go);
        cp16(dst + AVL + so, g_vl + go);
    }
}

__global__ void __launch_bounds__(256) attn_mma()
{
    extern __shared__ __align__(128) char smc[];
    const int tid = threadIdx.x, lane = tid & 31, warp = tid >> 5;
    const int qt = blockIdx.x, h = blockIdx.y, b = blockIdx.z;
    const int q0 = qt * 128;
    const size_t base = ((size_t)(b*NH + h)) * SEQ * HD;
    const uint32_t sb = smem_u32(smc);
    const int nkt = 2*qt + 2;

    // Q tiles via cp.async
    #pragma unroll
    for (int i = 0; i < 4; i++) {
        int c = tid + i * 256;            // 0..1023
        int r = c >> 3, c16 = c & 7;
        const size_t go = base + (size_t)(q0 + r) * HD + c16 * 8;
        cp16(sb + SM_Q  + (uint32_t)(r*ALDB + c16*16), g_qh + go);
        cp16(sb + SM_QL + (uint32_t)(r*ALDB + c16*16), g_ql + go);
    }
    load_kv_tile(sb + SM_KV, base, 0, tid);
    CP_COMMIT();

    float sf[8][4], acc[8][4];
    #pragma unroll
    for (int j = 0; j < 8; j++)
        #pragma unroll
        for (int r = 0; r < 4; r++) acc[j][r] = 0.f;
    float m0 = -1e30f, m1 = -1e30f, l0 = 0.f, l1 = 0.f;

    const int g = lane >> 2, tig = lane & 3;
    const int qr = warp * 16;
    const int gr0 = q0 + qr + g;          // row 0 (row 1 = gr0 + 8)

    const uint32_t aQoff = (uint32_t)((qr + (lane & 15)) * ALDB + ((lane >> 4) * 8) * 2);
    const uint32_t bKoff = (uint32_t)((((lane >> 4) & 1) * 8 + (lane & 7)) * ALDB
                                      + (((lane >> 3) & 1) * 8) * 2);
    const uint32_t vToff = (uint32_t)(((lane & 7) + ((lane >> 3) & 1) * 8) * ALDB
                                      + ((lane >> 4) * 8) * 2);

    for (int kt = 0; kt < nkt; kt++) {
        CP_WAIT0();
        __syncthreads();
        const uint32_t stg = sb + SM_KV + (uint32_t)(kt & 1) * STG_SZ;
        if (kt + 1 < nkt)
            load_kv_tile(sb + SM_KV + (uint32_t)((kt+1) & 1) * STG_SZ,
                         base, (kt+1)*64, tid);
        CP_COMMIT();

        // --- S = Q K^T (3-term bf16) ---
        #pragma unroll
        for (int j = 0; j < 8; j++)
            #pragma unroll
            for (int r = 0; r < 4; r++) sf[j][r] = 0.f;

        #pragma unroll
        for (int t = 0; t < 4; t++) {
            uint32_t ah[4], al[4];
            ldsm4(ah, sb + SM_Q  + aQoff + t*32);
            ldsm4(al, sb + SM_QL + aQoff + t*32);
            #pragma unroll
            for (int nn = 0; nn < 4; nn++) {
                uint32_t bh[4], bl[4];
                ldsm4(bh, stg + AKH + (uint32_t)(nn*16)*ALDB + bKoff + t*32);
                mma16816(sf[2*nn],   ah, bh[0], bh[1]);
                mma16816(sf[2*nn+1], ah, bh[2], bh[3]);
                mma16816(sf[2*nn],   al, bh[0], bh[1]);
                mma16816(sf[2*nn+1], al, bh[2], bh[3]);
                ldsm4(bl, stg + AKL + (uint32_t)(nn*16)*ALDB + bKoff + t*32);
                mma16816(sf[2*nn],   ah, bl[0], bl[1]);
                mma16816(sf[2*nn+1], ah, bl[2], bl[3]);
            }
        }

        // --- causal mask (scores are in log2e units already) ---
        const int k0 = kt * 64;
        if (k0 + 63 > gr0) {
            #pragma unroll
            for (int j = 0; j < 8; j++) {
                const int kc = k0 + 8*j + 2*tig;
                if (kc     > gr0)     sf[j][0] = -1e30f;
                if (kc + 1 > gr0)     sf[j][1] = -1e30f;
                if (kc     > gr0 + 8) sf[j][2] = -1e30f;
                if (kc + 1 > gr0 + 8) sf[j][3] = -1e30f;
            }
        }

        // --- online softmax ---
        float mx0 = -1e30f, mx1 = -1e30f;
        #pragma unroll
        for (int j = 0; j < 8; j++) {
            mx0 = fmaxf(mx0, fmaxf(sf[j][0], sf[j][1]));
            mx1 = fmaxf(mx1, fmaxf(sf[j][2], sf[j][3]));
        }
        mx0 = fmaxf(mx0, __shfl_xor_sync(0xffffffffu, mx0, 1));
        mx0 = fmaxf(mx0, __shfl_xor_sync(0xffffffffu, mx0, 2));
        mx1 = fmaxf(mx1, __shfl_xor_sync(0xffffffffu, mx1, 1));
        mx1 = fmaxf(mx1, __shfl_xor_sync(0xffffffffu, mx1, 2));
        const float mn0 = fmaxf(m0, mx0), mn1 = fmaxf(m1, mx1);
        const float a0 = fexp2(m0 - mn0), a1 = fexp2(m1 - mn1);
        m0 = mn0; m1 = mn1;
        float s0 = 0.f, s1 = 0.f;
        #pragma unroll
        for (int j = 0; j < 8; j++) {
            sf[j][0] = fexp2(sf[j][0] - mn0); s0 += sf[j][0];
            sf[j][1] = fexp2(sf[j][1] - mn0); s0 += sf[j][1];
            sf[j][2] = fexp2(sf[j][2] - mn1); s1 += sf[j][2];
            sf[j][3] = fexp2(sf[j][3] - mn1); s1 += sf[j][3];
        }
        s0 += __shfl_xor_sync(0xffffffffu, s0, 1);
        s0 += __shfl_xor_sync(0xffffffffu, s0, 2);
        s1 += __shfl_xor_sync(0xffffffffu, s1, 1);
        s1 += __shfl_xor_sync(0xffffffffu, s1, 2);
        l0 = l0 * a0 + s0; l1 = l1 * a1 + s1;
        #pragma unroll
        for (int j = 0; j < 8; j++) {
            acc[j][0] *= a0; acc[j][1] *= a0;
            acc[j][2] *= a1; acc[j][3] *= a1;
        }

        // --- O += P V (3-term bf16, P from S fragments) ---
        #pragma unroll
        for (int t = 0; t < 4; t++) {
            uint32_t ph[4], pl[4];
            psplit(sf[2*t][0],   sf[2*t][1],   ph[0], pl[0]);
            psplit(sf[2*t][2],   sf[2*t][3],   ph[1], pl[1]);
            psplit(sf[2*t+1][0], sf[2*t+1][1], ph[2], pl[2]);
            psplit(sf[2*t+1][2], sf[2*t+1][3], ph[3], pl[3]);
            #pragma unroll
            for (int nn = 0; nn < 4; nn++) {
                uint32_t vh[4], vl[4];
                ldsm4t(vh, stg + AVH + (uint32_t)(t*16)*ALDB + vToff + nn*32);
                mma16816(acc[2*nn],   ph, vh[0], vh[1]);
                mma16816(acc[2*nn+1], ph, vh[2], vh[3]);
                mma16816(acc[2*nn],   pl, vh[0], vh[1]);
                mma16816(acc[2*nn+1], pl, vh[2], vh[3]);
                ldsm4t(vl, stg + AVL + (uint32_t)(t*16)*ALDB + vToff + nn*32);
                mma16816(acc[2*nn],   ph, vl[0], vl[1]);
                mma16816(acc[2*nn+1], ph, vl[2], vl[3]);
            }
        }
    }

    // --- epilogue: normalize, split to bf16 hi/lo, write y [B,S,D] ---
    const float il0 = 1.0f / l0, il1 = 1.0f / l1;
    const size_t o0 = ((size_t)(b*SEQ + gr0)) * D_M + h*HD;
    const size_t o1 = o0 + (size_t)8 * D_M;
    #pragma unroll
    for (int j = 0; j < 8; j++) {
        const int c = 8*j + 2*tig;
        uint32_t hi, lo;
        psplit(acc[j][0]*il0, acc[j][1]*il0, hi, lo);
        *(uint32_t*)(g_yhi + o0 + c) = hi; *(uint32_t*)(g_ylo + o0 + c) = lo;
        psplit(acc[j][2]*il1, acc[j][3]*il1, hi, lo);
        *(uint32_t*)(g_yhi + o1 + c) = hi; *(uint32_t*)(g_ylo + o1 + c) = lo;
    }
}

// ---------------------------------------------------------------------------
extern "C" void kernel_launch(void* const* d_in, const int* in_sizes, int n_in,
                              void* d_out, int out_size)
{
    const float* x  = (const float*)d_in[0];
    const float* Wq = (const float*)d_in[1];
    const float* bq = (const float*)d_in[2];
    const float* Wk = (const float*)d_in[3];
    const float* bk = (const float*)d_in[4];
    const float* Wv = (const float*)d_in[5];
    const float* bv = (const float*)d_in[6];
    const float* Wo = (const float*)d_in[7];
    const float* bo = (const float*)d_in[8];
    float* out = (float*)d_out;

    __nv_bfloat16 *qh, *ql, *kh, *kl, *vh, *vl, *xhi, *xlo, *yhi, *ylo, *wh, *wl;
    cudaGetSymbolAddress((void**)&qh, g_qh);
    cudaGetSymbolAddress((void**)&ql, g_ql);
    cudaGetSymbolAddress((void**)&kh, g_kh);
    cudaGetSymbolAddress((void**)&kl, g_kl);
    cudaGetSymbolAddress((void**)&vh, g_vh);
    cudaGetSymbolAddress((void**)&vl, g_vl);
    cudaGetSymbolAddress((void**)&xhi, g_xhi);
    cudaGetSymbolAddress((void**)&xlo, g_xlo);
    cudaGetSymbolAddress((void**)&yhi, g_yhi);
    cudaGetSymbolAddress((void**)&ylo, g_ylo);
    cudaGetSymbolAddress((void**)&wh, g_wh);
    cudaGetSymbolAddress((void**)&wl, g_wl);
    const size_t WSZ = (size_t)D_M * D_M;

    const int n4x = MTOT * D_M / 4;
    const int n4w = D_M * D_M / 4;
    split_kernel<<<n4x/256, 256>>>(x,  xhi, xlo, n4x);
    split_kernel<<<n4w/256, 256>>>(Wq, wh + 0*WSZ, wl + 0*WSZ, n4w);
    split_kernel<<<n4w/256, 256>>>(Wk, wh + 1*WSZ, wl + 1*WSZ, n4w);
    split_kernel<<<n4w/256, 256>>>(Wv, wh + 2*WSZ, wl + 2*WSZ, n4w);
    split_kernel<<<n4w/256, 256>>>(Wo, wh + 3*WSZ, wl + 3*WSZ, n4w);

    cudaFuncSetAttribute(gemm_mma,
                         cudaFuncAttributeMaxDynamicSharedMemorySize, SMEM_GEMM);
    cudaFuncSetAttribute(attn_mma,
                         cudaFuncAttributeMaxDynamicSharedMemorySize, ATTN_SMEM);

    // scale for Q: (1/sqrt(hd)) * log2(e), folded so attention uses exp2
    const float qscale = 0.125f * 1.4426950408889634f;
    dim3 gg(MTOT/128, D_M/128);
    gemm_mma<<<gg, 256, SMEM_GEMM>>>(xhi, xlo, wh + 0*WSZ, wl + 0*WSZ, bq,
                                     qh, ql, nullptr, 0, qscale);
    gemm_mma<<<gg, 256, SMEM_GEMM>>>(xhi, xlo, wh + 1*WSZ, wl + 1*WSZ, bk,
                                     kh, kl, nullptr, 0, 1.0f);
    gemm_mma<<<gg, 256, SMEM_GEMM>>>(xhi, xlo, wh + 2*WSZ, wl + 2*WSZ, bv,
                                     vh, vl, nullptr, 0, 1.0f);

    attn_mma<<<dim3(SEQ/128, NH, BATCH), 256, ATTN_SMEM>>>();

    gemm_mma<<<gg, 256, SMEM_GEMM>>>(yhi, ylo, wh + 3*WSZ, wl + 3*WSZ, bo,
                                     nullptr, nullptr, out, 1, 1.0f);
}

// round 5
// speedup vs baseline: 2.9792x; 1.1515x over previous
#include <cuda_runtime.h>
#include <cuda_bf16.h>
#include <math.h>
#include <stdint.h>

#define D_M   1024
#define NH    16
#define HD    64
#define BATCH 4
#define SEQ   2048
#define MTOT  (BATCH*SEQ)
#define AOFF  ((size_t)MTOT*D_M)     // hi->lo offset in paired activation arrays
#define WOFF  ((size_t)D_M*D_M)      // hi->lo offset in paired weight arrays

// ---------------- device scratch (no allocation allowed) -------------------
__device__ __align__(16) __nv_bfloat16 g_qh[(size_t)BATCH*NH*SEQ*HD];
__device__ __align__(16) __nv_bfloat16 g_ql[(size_t)BATCH*NH*SEQ*HD];
__device__ __align__(16) __nv_bfloat16 g_kh[(size_t)BATCH*NH*SEQ*HD];
__device__ __align__(16) __nv_bfloat16 g_kl[(size_t)BATCH*NH*SEQ*HD];
__device__ __align__(16) __nv_bfloat16 g_vh[(size_t)BATCH*NH*SEQ*HD];
__device__ __align__(16) __nv_bfloat16 g_vl[(size_t)BATCH*NH*SEQ*HD];
__device__ __align__(16) __nv_bfloat16 g_x2[2*(size_t)MTOT*D_M];   // xhi | xlo
__device__ __align__(16) __nv_bfloat16 g_y2[2*(size_t)MTOT*D_M];   // yhi | ylo
__device__ __align__(16) __nv_bfloat16 g_w2[4][2*(size_t)D_M*D_M]; // whi | wlo

// ---------------- helpers ----------------------------------------------------
__device__ __forceinline__ uint32_t smem_u32(const void* p) {
    uint32_t a;
    asm("{ .reg .u64 t; cvta.to.shared.u64 t, %1; cvt.u32.u64 %0, t; }"
        : "=r"(a) : "l"(p));
    return a;
}
__device__ __forceinline__ void cp16(uint32_t s, const void* g) {
    asm volatile("cp.async.cg.shared.global [%0], [%1], 16;"
                 :: "r"(s), "l"(g) : "memory");
}
#define CP_COMMIT() asm volatile("cp.async.commit_group;" ::: "memory")
#define CP_WAIT1()  asm volatile("cp.async.wait_group 1;" ::: "memory")
#define CP_WAIT0()  asm volatile("cp.async.wait_group 0;" ::: "memory")

__device__ __forceinline__ void ldsm4(uint32_t* r, uint32_t addr) {
    asm volatile("ldmatrix.sync.aligned.m8n8.x4.shared.b16 {%0,%1,%2,%3}, [%4];"
                 : "=r"(r[0]), "=r"(r[1]), "=r"(r[2]), "=r"(r[3]) : "r"(addr));
}
__device__ __forceinline__ void ldsm4t(uint32_t* r, uint32_t addr) {
    asm volatile("ldmatrix.sync.aligned.m8n8.x4.trans.shared.b16 {%0,%1,%2,%3}, [%4];"
                 : "=r"(r[0]), "=r"(r[1]), "=r"(r[2]), "=r"(r[3]) : "r"(addr));
}
__device__ __forceinline__ void mma16816(float* c, const uint32_t* a,
                                         uint32_t b0, uint32_t b1) {
    asm volatile(
        "mma.sync.aligned.m16n8k16.row.col.f32.bf16.bf16.f32 "
        "{%0,%1,%2,%3}, {%4,%5,%6,%7}, {%8,%9}, {%0,%1,%2,%3};"
        : "+f"(c[0]), "+f"(c[1]), "+f"(c[2]), "+f"(c[3])
        : "r"(a[0]), "r"(a[1]), "r"(a[2]), "r"(a[3]), "r"(b0), "r"(b1));
}
// fast exp2 on FMA pipe (deg-5 poly, rel err ~2.4e-6)
__device__ __forceinline__ float fexp2(float t) {
    t = fmaxf(t, -126.0f);
    float z  = t + 12582912.0f;
    int   n  = __float_as_int(z);
    float fn = z - 12582912.0f;
    float f  = t - fn;
    float p  =       1.3333558146e-3f;
    p = fmaf(p, f,   9.6181291076e-3f);
    p = fmaf(p, f,   5.5504108664e-2f);
    p = fmaf(p, f,   2.4022650696e-1f);
    p = fmaf(p, f,   6.9314718056e-1f);
    p = fmaf(p, f,   1.0f);
    return __int_as_float(__float_as_int(p) + (n << 23));
}
__device__ __forceinline__ void psplit(float a, float b, uint32_t& hi, uint32_t& lo) {
    __nv_bfloat16 ha = __float2bfloat16_rn(a), hb = __float2bfloat16_rn(b);
    __nv_bfloat16 la = __float2bfloat16_rn(a - __bfloat162float(ha));
    __nv_bfloat16 lb = __float2bfloat16_rn(b - __bfloat162float(hb));
    __nv_bfloat162 H = __halves2bfloat162(ha, hb), L = __halves2bfloat162(la, lb);
    hi = *(uint32_t*)&H; lo = *(uint32_t*)&L;
}

// ---------------- fp32 -> bf16 hi/lo split ----------------------------------
__global__ void __launch_bounds__(256) split_kernel(
    const float* __restrict__ src, __nv_bfloat16* __restrict__ hi,
    __nv_bfloat16* __restrict__ lo, int n4)
{
    int i = blockIdx.x * 256 + threadIdx.x;
    if (i >= n4) return;
    float4 v = ((const float4*)src)[i];
    uint32_t h0, l0, h1, l1;
    psplit(v.x, v.y, h0, l0);
    psplit(v.z, v.w, h1, l1);
    ((uint32_t*)hi)[2*i]   = h0; ((uint32_t*)hi)[2*i+1] = h1;
    ((uint32_t*)lo)[2*i]   = l0; ((uint32_t*)lo)[2*i+1] = l1;
}

// ---------------- mma.sync bf16x3 GEMM, 2-stage, 2 CTA/SM -------------------
// out[m,n] = (sum_k A[m,k]*W[n,k] + bias[n]) * outscale
// A lo implicit at A+AOFF, W lo implicit at W+WOFF.
#define BKG     32
#define LDT     40
#define TILE_B  (128*LDT*2)            // 10240 B
#define STAGE_B (4*TILE_B)             // 40960 B (Ahi, Alo, Whi, Wlo)
#define SMEM_GEMM (2*STAGE_B)          // 81920 B -> 2 CTAs/SM

__global__ void __launch_bounds__(256, 2) gemm_mma(
    const __nv_bfloat16* __restrict__ A, const __nv_bfloat16* __restrict__ W,
    const float* __restrict__ bias,
    __nv_bfloat16* __restrict__ dsth, __nv_bfloat16* __restrict__ dstl,
    float* __restrict__ fdst, int mode, float outscale)
{
    extern __shared__ __align__(128) char smem[];
    const int tid  = threadIdx.x;
    const int warp = tid >> 5, lane = tid & 31;
    const int m0 = blockIdx.x * 128, n0 = blockIdx.y * 128;
    const int wm = warp >> 2, wn = warp & 3;
    const uint32_t sb = smem_u32(smem);

    // per-thread load descriptors: ids 0..511 cover one 128x32 tile
    uint32_t soff0[2]; const __nv_bfloat16 *srcA[2], *srcW[2];
    #pragma unroll
    for (int i = 0; i < 2; i++) {
        int idx = tid + i * 256;            // 0..511
        int row = idx >> 2, c = idx & 3;
        soff0[i] = (uint32_t)(row * (LDT*2) + c * 16);
        srcA[i] = A + (size_t)(m0 + row) * D_M + c * 8;
        srcW[i] = W + (size_t)(n0 + row) * D_M + c * 8;
    }

    float acc[4][4][4];
    #pragma unroll
    for (int mi = 0; mi < 4; mi++)
        #pragma unroll
        for (int ni = 0; ni < 4; ni++)
            #pragma unroll
            for (int r = 0; r < 4; r++) acc[mi][ni][r] = 0.f;

    const int a_row  = wm * 64 + (lane & 15);
    const int a_col8 = (lane >> 4);
    const int bg = lane >> 3, b_in = lane & 7;
    const int b_row  = wn * 32 + (bg >> 1) * 8 + b_in;
    const int b_k8   = bg & 1;

    // prologue: chunks 0,1 into stages 0,1
    #pragma unroll
    for (int p = 0; p < 2; p++) {
        const uint32_t dstg = sb + p * STAGE_B;
        #pragma unroll
        for (int i = 0; i < 2; i++) {
            cp16(dstg + soff0[i],            srcA[i] + p*BKG);
            cp16(dstg + soff0[i] +   TILE_B, srcA[i] + AOFF + p*BKG);
            cp16(dstg + soff0[i] + 2*TILE_B, srcW[i] + p*BKG);
            cp16(dstg + soff0[i] + 3*TILE_B, srcW[i] + WOFF + p*BKG);
        }
        CP_COMMIT();
    }

    for (int kt = 0; kt < 32; kt++) {
        CP_WAIT1();                   // all but most-recent group complete
        __syncthreads();

        const uint32_t stg = sb + (uint32_t)(kt & 1) * STAGE_B;
        #pragma unroll
        for (int kk = 0; kk < 2; kk++) {
            const uint32_t acol = (uint32_t)((kk * 16 + a_col8 * 8) * 2);
            const uint32_t bcol = (uint32_t)((kk * 16 + b_k8 * 8) * 2);
            uint32_t ah[4][4], al[4][4], wh_[2][4], wl_[2][4];
            #pragma unroll
            for (int mi = 0; mi < 4; mi++)
                ldsm4(ah[mi], stg + (a_row + mi*16) * (LDT*2) + acol);
            #pragma unroll
            for (int pi = 0; pi < 2; pi++)
                ldsm4(wh_[pi], stg + 2*TILE_B + (b_row + pi*16) * (LDT*2) + bcol);
            #pragma unroll
            for (int mi = 0; mi < 4; mi++)
                #pragma unroll
                for (int ni = 0; ni < 4; ni++)
                    mma16816(acc[mi][ni], ah[mi],
                             wh_[ni>>1][(ni&1)*2], wh_[ni>>1][(ni&1)*2+1]);
            #pragma unroll
            for (int mi = 0; mi < 4; mi++)
                ldsm4(al[mi], stg + TILE_B + (a_row + mi*16) * (LDT*2) + acol);
            #pragma unroll
            for (int mi = 0; mi < 4; mi++)
                #pragma unroll
                for (int ni = 0; ni < 4; ni++)
                    mma16816(acc[mi][ni], al[mi],
                             wh_[ni>>1][(ni&1)*2], wh_[ni>>1][(ni&1)*2+1]);
            #pragma unroll
            for (int pi = 0; pi < 2; pi++)
                ldsm4(wl_[pi], stg + 3*TILE_B + (b_row + pi*16) * (LDT*2) + bcol);
            #pragma unroll
            for (int mi = 0; mi < 4; mi++)
                #pragma unroll
                for (int ni = 0; ni < 4; ni++)
                    mma16816(acc[mi][ni], ah[mi],
                             wl_[ni>>1][(ni&1)*2], wl_[ni>>1][(ni&1)*2+1]);
        }
        __syncthreads();              // stage kt&1 fully consumed

        if (kt < 30) {
            const int kn = kt + 2;
            const uint32_t dstg = sb + (uint32_t)(kt & 1) * STAGE_B;
            #pragma unroll
            for (int i = 0; i < 2; i++) {
                cp16(dstg + soff0[i],            srcA[i] + kn*BKG);
                cp16(dstg + soff0[i] +   TILE_B, srcA[i] + AOFF + kn*BKG);
                cp16(dstg + soff0[i] + 2*TILE_B, srcW[i] + kn*BKG);
                cp16(dstg + soff0[i] + 3*TILE_B, srcW[i] + WOFF + kn*BKG);
            }
        }
        CP_COMMIT();                  // commit every iter (positional wait)
    }

    #pragma unroll
    for (int mi = 0; mi < 4; mi++) {
        #pragma unroll
        for (int ni = 0; ni < 4; ni++) {
            const int m_a = m0 + wm*64 + mi*16 + (lane >> 2);
            const int n_a = n0 + wn*32 + ni*8 + (lane & 3)*2;
            const float b0 = bias[n_a], b1 = bias[n_a + 1];
            const float v00 = (acc[mi][ni][0] + b0) * outscale;
            const float v01 = (acc[mi][ni][1] + b1) * outscale;
            const float v10 = (acc[mi][ni][2] + b0) * outscale;
            const float v11 = (acc[mi][ni][3] + b1) * outscale;
            if (mode == 0) {
                const int h = n_a >> 6, d = n_a & 63;
                const int b  = m_a >> 11, s  = m_a & 2047;
                const int b2 = (m_a+8) >> 11, s2 = (m_a+8) & 2047;
                const size_t i0 = (((size_t)(b *NH + h))*SEQ + s )*HD + d;
                const size_t i1 = (((size_t)(b2*NH + h))*SEQ + s2)*HD + d;
                uint32_t hi, lo;
                psplit(v00, v01, hi, lo);
                *(uint32_t*)(dsth + i0) = hi; *(uint32_t*)(dstl + i0) = lo;
                psplit(v10, v11, hi, lo);
                *(uint32_t*)(dsth + i1) = hi; *(uint32_t*)(dstl + i1) = lo;
            } else {
                *(float2*)&fdst[(size_t)m_a     * D_M + n_a] = make_float2(v00, v01);
                *(float2*)&fdst[(size_t)(m_a+8) * D_M + n_a] = make_float2(v10, v11);
            }
        }
    }
}

// ---------------- flash attention, bf16x3 mma.sync, 2 CTA/SM ----------------
#define ALDB 144
#define SM_Q    0
#define SM_QL   (128*ALDB)
#define SM_KV   (2*128*ALDB)
#define STG_SZ  (4*64*ALDB)
#define AKH     0
#define AKL     (64*ALDB)
#define AVH     (2*64*ALDB)
#define AVL     (3*64*ALDB)
#define ATTN_SMEM (SM_KV + 2*STG_SZ)   // 110592 B

__device__ __forceinline__ void load_kv_tile(uint32_t dst, size_t gbase,
                                             int k0, int tid)
{
    #pragma unroll
    for (int i = 0; i < 2; i++) {
        int c = tid + i * 256;
        int r = c >> 3, c16 = c & 7;
        const size_t go = gbase + (size_t)(k0 + r) * HD + c16 * 8;
        const uint32_t so = (uint32_t)(r * ALDB + c16 * 16);
        cp16(dst + AKH + so, g_kh + go);
        cp16(dst + AKL + so, g_kl + go);
        cp16(dst + AVH + so, g_vh + go);
        cp16(dst + AVL + so, g_vl + go);
    }
}

__global__ void __launch_bounds__(256, 2) attn_mma()
{
    extern __shared__ __align__(128) char smc[];
    const int tid = threadIdx.x, lane = tid & 31, warp = tid >> 5;
    const int qt = blockIdx.x, h = blockIdx.y, b = blockIdx.z;
    const int q0 = qt * 128;
    const size_t base = ((size_t)(b*NH + h)) * SEQ * HD;
    const uint32_t sb = smem_u32(smc);
    const int nkt = 2*qt + 2;

    #pragma unroll
    for (int i = 0; i < 4; i++) {
        int c = tid + i * 256;
        int r = c >> 3, c16 = c & 7;
        const size_t go = base + (size_t)(q0 + r) * HD + c16 * 8;
        cp16(sb + SM_Q  + (uint32_t)(r*ALDB + c16*16), g_qh + go);
        cp16(sb + SM_QL + (uint32_t)(r*ALDB + c16*16), g_ql + go);
    }
    load_kv_tile(sb + SM_KV, base, 0, tid);
    CP_COMMIT();

    float sf[8][4], acc[8][4];
    #pragma unroll
    for (int j = 0; j < 8; j++)
        #pragma unroll
        for (int r = 0; r < 4; r++) acc[j][r] = 0.f;
    float m0 = -1e30f, m1 = -1e30f, l0 = 0.f, l1 = 0.f;

    const int g = lane >> 2, tig = lane & 3;
    const int qr = warp * 16;
    const int gr0 = q0 + qr + g;

    const uint32_t aQoff = (uint32_t)((qr + (lane & 15)) * ALDB + ((lane >> 4) * 8) * 2);
    const uint32_t bKoff = (uint32_t)((((lane >> 4) & 1) * 8 + (lane & 7)) * ALDB
                                      + (((lane >> 3) & 1) * 8) * 2);
    const uint32_t vToff = (uint32_t)(((lane & 7) + ((lane >> 3) & 1) * 8) * ALDB
                                      + ((lane >> 4) * 8) * 2);

    for (int kt = 0; kt < nkt; kt++) {
        CP_WAIT0();
        __syncthreads();
        const uint32_t stg = sb + SM_KV + (uint32_t)(kt & 1) * STG_SZ;
        if (kt + 1 < nkt)
            load_kv_tile(sb + SM_KV + (uint32_t)((kt+1) & 1) * STG_SZ,
                         base, (kt+1)*64, tid);
        CP_COMMIT();

        #pragma unroll
        for (int j = 0; j < 8; j++)
            #pragma unroll
            for (int r = 0; r < 4; r++) sf[j][r] = 0.f;

        #pragma unroll
        for (int t = 0; t < 4; t++) {
            uint32_t ah[4], al[4];
            ldsm4(ah, sb + SM_Q  + aQoff + t*32);
            ldsm4(al, sb + SM_QL + aQoff + t*32);
            #pragma unroll
            for (int nn = 0; nn < 4; nn++) {
                uint32_t bh[4], bl[4];
                ldsm4(bh, stg + AKH + (uint32_t)(nn*16)*ALDB + bKoff + t*32);
                mma16816(sf[2*nn],   ah, bh[0], bh[1]);
                mma16816(sf[2*nn+1], ah, bh[2], bh[3]);
                mma16816(sf[2*nn],   al, bh[0], bh[1]);
                mma16816(sf[2*nn+1], al, bh[2], bh[3]);
                ldsm4(bl, stg + AKL + (uint32_t)(nn*16)*ALDB + bKoff + t*32);
                mma16816(sf[2*nn],   ah, bl[0], bl[1]);
                mma16816(sf[2*nn+1], ah, bl[2], bl[3]);
            }
        }

        const int k0 = kt * 64;
        if (k0 + 63 > gr0) {
            #pragma unroll
            for (int j = 0; j < 8; j++) {
                const int kc = k0 + 8*j + 2*tig;
                if (kc     > gr0)     sf[j][0] = -1e30f;
                if (kc + 1 > gr0)     sf[j][1] = -1e30f;
                if (kc     > gr0 + 8) sf[j][2] = -1e30f;
                if (kc + 1 > gr0 + 8) sf[j][3] = -1e30f;
            }
        }

        float mx0 = -1e30f, mx1 = -1e30f;
        #pragma unroll
        for (int j = 0; j < 8; j++) {
            mx0 = fmaxf(mx0, fmaxf(sf[j][0], sf[j][1]));
            mx1 = fmaxf(mx1, fmaxf(sf[j][2], sf[j][3]));
        }
        mx0 = fmaxf(mx0, __shfl_xor_sync(0xffffffffu, mx0, 1));
        mx0 = fmaxf(mx0, __shfl_xor_sync(0xffffffffu, mx0, 2));
        mx1 = fmaxf(mx1, __shfl_xor_sync(0xffffffffu, mx1, 1));
        mx1 = fmaxf(mx1, __shfl_xor_sync(0xffffffffu, mx1, 2));
        const float mn0 = fmaxf(m0, mx0), mn1 = fmaxf(m1, mx1);
        const float a0 = fexp2(m0 - mn0), a1 = fexp2(m1 - mn1);
        m0 = mn0; m1 = mn1;
        float s0 = 0.f, s1 = 0.f;
        #pragma unroll
        for (int j = 0; j < 8; j++) {
            sf[j][0] = fexp2(sf[j][0] - mn0); s0 += sf[j][0];
            sf[j][1] = fexp2(sf[j][1] - mn0); s0 += sf[j][1];
            sf[j][2] = fexp2(sf[j][2] - mn1); s1 += sf[j][2];
            sf[j][3] = fexp2(sf[j][3] - mn1); s1 += sf[j][3];
        }
        s0 += __shfl_xor_sync(0xffffffffu, s0, 1);
        s0 += __shfl_xor_sync(0xffffffffu, s0, 2);
        s1 += __shfl_xor_sync(0xffffffffu, s1, 1);
        s1 += __shfl_xor_sync(0xffffffffu, s1, 2);
        l0 = l0 * a0 + s0; l1 = l1 * a1 + s1;
        #pragma unroll
        for (int j = 0; j < 8; j++) {
            acc[j][0] *= a0; acc[j][1] *= a0;
            acc[j][2] *= a1; acc[j][3] *= a1;
        }

        #pragma unroll
        for (int t = 0; t < 4; t++) {
            uint32_t ph[4], pl[4];
            psplit(sf[2*t][0],   sf[2*t][1],   ph[0], pl[0]);
            psplit(sf[2*t][2],   sf[2*t][3],   ph[1], pl[1]);
            psplit(sf[2*t+1][0], sf[2*t+1][1], ph[2], pl[2]);
            psplit(sf[2*t+1][2], sf[2*t+1][3], ph[3], pl[3]);
            #pragma unroll
            for (int nn = 0; nn < 4; nn++) {
                uint32_t vh[4], vl[4];
                ldsm4t(vh, stg + AVH + (uint32_t)(t*16)*ALDB + vToff + nn*32);
                mma16816(acc[2*nn],   ph, vh[0], vh[1]);
                mma16816(acc[2*nn+1], ph, vh[2], vh[3]);
                mma16816(acc[2*nn],   pl, vh[0], vh[1]);
                mma16816(acc[2*nn+1], pl, vh[2], vh[3]);
                ldsm4t(vl, stg + AVL + (uint32_t)(t*16)*ALDB + vToff + nn*32);
                mma16816(acc[2*nn],   ph, vl[0], vl[1]);
                mma16816(acc[2*nn+1], ph, vl[2], vl[3]);
            }
        }
    }

    const float il0 = 1.0f / l0, il1 = 1.0f / l1;
    const size_t o0 = ((size_t)(b*SEQ + gr0)) * D_M + h*HD;
    const size_t o1 = o0 + (size_t)8 * D_M;
    #pragma unroll
    for (int j = 0; j < 8; j++) {
        const int c = 8*j + 2*tig;
        uint32_t hi, lo;
        psplit(acc[j][0]*il0, acc[j][1]*il0, hi, lo);
        *(uint32_t*)(g_y2 + o0 + c) = hi; *(uint32_t*)(g_y2 + AOFF + o0 + c) = lo;
        psplit(acc[j][2]*il1, acc[j][3]*il1, hi, lo);
        *(uint32_t*)(g_y2 + o1 + c) = hi; *(uint32_t*)(g_y2 + AOFF + o1 + c) = lo;
    }
}

// ---------------------------------------------------------------------------
extern "C" void kernel_launch(void* const* d_in, const int* in_sizes, int n_in,
                              void* d_out, int out_size)
{
    const float* x  = (const float*)d_in[0];
    const float* Wq = (const float*)d_in[1];
    const float* bq = (const float*)d_in[2];
    const float* Wk = (const float*)d_in[3];
    const float* bk = (const float*)d_in[4];
    const float* Wv = (const float*)d_in[5];
    const float* bv = (const float*)d_in[6];
    const float* Wo = (const float*)d_in[7];
    const float* bo = (const float*)d_in[8];
    float* out = (float*)d_out;

    __nv_bfloat16 *qh, *ql, *kh, *kl, *vh, *vl, *x2, *y2, *w2;
    cudaGetSymbolAddress((void**)&qh, g_qh);
    cudaGetSymbolAddress((void**)&ql, g_ql);
    cudaGetSymbolAddress((void**)&kh, g_kh);
    cudaGetSymbolAddress((void**)&kl, g_kl);
    cudaGetSymbolAddress((void**)&vh, g_vh);
    cudaGetSymbolAddress((void**)&vl, g_vl);
    cudaGetSymbolAddress((void**)&x2, g_x2);
    cudaGetSymbolAddress((void**)&y2, g_y2);
    cudaGetSymbolAddress((void**)&w2, g_w2);

    const int n4x = MTOT * D_M / 4;
    const int n4w = D_M * D_M / 4;
    split_kernel<<<n4x/256, 256>>>(x,  x2, x2 + AOFF, n4x);
    split_kernel<<<n4w/256, 256>>>(Wq, w2 + 0*2*WOFF, w2 + 0*2*WOFF + WOFF, n4w);
    split_kernel<<<n4w/256, 256>>>(Wk, w2 + 1*2*WOFF, w2 + 1*2*WOFF + WOFF, n4w);
    split_kernel<<<n4w/256, 256>>>(Wv, w2 + 2*2*WOFF, w2 + 2*2*WOFF + WOFF, n4w);
    split_kernel<<<n4w/256, 256>>>(Wo, w2 + 3*2*WOFF, w2 + 3*2*WOFF + WOFF, n4w);

    cudaFuncSetAttribute(gemm_mma,
                         cudaFuncAttributeMaxDynamicSharedMemorySize, SMEM_GEMM);
    cudaFuncSetAttribute(attn_mma,
                         cudaFuncAttributeMaxDynamicSharedMemorySize, ATTN_SMEM);

    const float qscale = 0.125f * 1.4426950408889634f;
    dim3 gg(MTOT/128, D_M/128);
    gemm_mma<<<gg, 256, SMEM_GEMM>>>(x2, w2 + 0*2*WOFF, bq, qh, ql, nullptr, 0, qscale);
    gemm_mma<<<gg, 256, SMEM_GEMM>>>(x2, w2 + 1*2*WOFF, bk, kh, kl, nullptr, 0, 1.0f);
    gemm_mma<<<gg, 256, SMEM_GEMM>>>(x2, w2 + 2*2*WOFF, bv, vh, vl, nullptr, 0, 1.0f);

    attn_mma<<<dim3(SEQ/128, NH, BATCH), 256, ATTN_SMEM>>>();

    gemm_mma<<<gg, 256, SMEM_GEMM>>>(y2, w2 + 3*2*WOFF, bo, nullptr, nullptr, out, 1, 1.0f);
}

// round 6
// speedup vs baseline: 3.0934x; 1.0383x over previous
#include <cuda_runtime.h>
#include <cuda_bf16.h>
#include <math.h>
#include <stdint.h>

#define D_M   1024
#define NH    16
#define HD    64
#define BATCH 4
#define SEQ   2048
#define MTOT  (BATCH*SEQ)
#define AOFF  ((size_t)MTOT*D_M)     // hi->lo offset in paired activation arrays
#define WOFF  ((size_t)D_M*D_M)      // hi->lo offset in paired weight arrays

// ---------------- device scratch (no allocation allowed) -------------------
__device__ __align__(16) __nv_bfloat16 g_qh[(size_t)BATCH*NH*SEQ*HD];
__device__ __align__(16) __nv_bfloat16 g_ql[(size_t)BATCH*NH*SEQ*HD];
__device__ __align__(16) __nv_bfloat16 g_kh[(size_t)BATCH*NH*SEQ*HD];
__device__ __align__(16) __nv_bfloat16 g_kl[(size_t)BATCH*NH*SEQ*HD];
__device__ __align__(16) __nv_bfloat16 g_vh[(size_t)BATCH*NH*SEQ*HD];
__device__ __align__(16) __nv_bfloat16 g_vl[(size_t)BATCH*NH*SEQ*HD];
__device__ __align__(16) __nv_bfloat16 g_x2[2*(size_t)MTOT*D_M];   // xhi | xlo
__device__ __align__(16) __nv_bfloat16 g_y2[2*(size_t)MTOT*D_M];   // yhi | ylo
__device__ __align__(16) __nv_bfloat16 g_w2[4][2*(size_t)D_M*D_M]; // whi | wlo

// ---------------- helpers ----------------------------------------------------
__device__ __forceinline__ uint32_t smem_u32(const void* p) {
    uint32_t a;
    asm("{ .reg .u64 t; cvta.to.shared.u64 t, %1; cvt.u32.u64 %0, t; }"
        : "=r"(a) : "l"(p));
    return a;
}
__device__ __forceinline__ void cp16(uint32_t s, const void* g) {
    asm volatile("cp.async.cg.shared.global [%0], [%1], 16;"
                 :: "r"(s), "l"(g) : "memory");
}
#define CP_COMMIT() asm volatile("cp.async.commit_group;" ::: "memory")
#define CP_WAIT1()  asm volatile("cp.async.wait_group 1;" ::: "memory")
#define CP_WAIT0()  asm volatile("cp.async.wait_group 0;" ::: "memory")

__device__ __forceinline__ void ldsm4(uint32_t* r, uint32_t addr) {
    asm volatile("ldmatrix.sync.aligned.m8n8.x4.shared.b16 {%0,%1,%2,%3}, [%4];"
                 : "=r"(r[0]), "=r"(r[1]), "=r"(r[2]), "=r"(r[3]) : "r"(addr));
}
__device__ __forceinline__ void ldsm4t(uint32_t* r, uint32_t addr) {
    asm volatile("ldmatrix.sync.aligned.m8n8.x4.trans.shared.b16 {%0,%1,%2,%3}, [%4];"
                 : "=r"(r[0]), "=r"(r[1]), "=r"(r[2]), "=r"(r[3]) : "r"(addr));
}
__device__ __forceinline__ void mma16816(float* c, const uint32_t* a,
                                         uint32_t b0, uint32_t b1) {
    asm volatile(
        "mma.sync.aligned.m16n8k16.row.col.f32.bf16.bf16.f32 "
        "{%0,%1,%2,%3}, {%4,%5,%6,%7}, {%8,%9}, {%0,%1,%2,%3};"
        : "+f"(c[0]), "+f"(c[1]), "+f"(c[2]), "+f"(c[3])
        : "r"(a[0]), "r"(a[1]), "r"(a[2]), "r"(a[3]), "r"(b0), "r"(b1));
}
__device__ __forceinline__ float fexp2(float t) {
    t = fmaxf(t, -126.0f);
    float z  = t + 12582912.0f;
    int   n  = __float_as_int(z);
    float fn = z - 12582912.0f;
    float f  = t - fn;
    float p  =       1.3333558146e-3f;
    p = fmaf(p, f,   9.6181291076e-3f);
    p = fmaf(p, f,   5.5504108664e-2f);
    p = fmaf(p, f,   2.4022650696e-1f);
    p = fmaf(p, f,   6.9314718056e-1f);
    p = fmaf(p, f,   1.0f);
    return __int_as_float(__float_as_int(p) + (n << 23));
}
__device__ __forceinline__ void psplit(float a, float b, uint32_t& hi, uint32_t& lo) {
    __nv_bfloat16 ha = __float2bfloat16_rn(a), hb = __float2bfloat16_rn(b);
    __nv_bfloat16 la = __float2bfloat16_rn(a - __bfloat162float(ha));
    __nv_bfloat16 lb = __float2bfloat16_rn(b - __bfloat162float(hb));
    __nv_bfloat162 H = __halves2bfloat162(ha, hb), L = __halves2bfloat162(la, lb);
    hi = *(uint32_t*)&H; lo = *(uint32_t*)&L;
}

// ---------------- fp32 -> bf16 hi/lo splits ----------------------------------
__global__ void __launch_bounds__(256) split_kernel(
    const float* __restrict__ src, __nv_bfloat16* __restrict__ hi,
    __nv_bfloat16* __restrict__ lo, int n4)
{
    int i = blockIdx.x * 256 + threadIdx.x;
    if (i >= n4) return;
    float4 v = ((const float4*)src)[i];
    uint32_t h0, l0, h1, l1;
    psplit(v.x, v.y, h0, l0);
    psplit(v.z, v.w, h1, l1);
    ((uint32_t*)hi)[2*i]   = h0; ((uint32_t*)hi)[2*i+1] = h1;
    ((uint32_t*)lo)[2*i]   = l0; ((uint32_t*)lo)[2*i+1] = l1;
}
// all four weight matrices in one launch (w index = i >> 18)
__global__ void __launch_bounds__(256) split_w_kernel(
    const float* __restrict__ w0, const float* __restrict__ w1,
    const float* __restrict__ w2s, const float* __restrict__ w3,
    __nv_bfloat16* __restrict__ wdst)
{
    int i = blockIdx.x * 256 + threadIdx.x;      // 0 .. 4*262144-1
    const int w = i >> 18, local = i & 262143;
    const float* src = (w == 0) ? w0 : (w == 1) ? w1 : (w == 2) ? w2s : w3;
    float4 v = ((const float4*)src)[local];
    uint32_t h0, l0, h1, l1;
    psplit(v.x, v.y, h0, l0);
    psplit(v.z, v.w, h1, l1);
    __nv_bfloat16* hi = wdst + (size_t)w * 2 * WOFF;
    __nv_bfloat16* lo = hi + WOFF;
    ((uint32_t*)hi)[2*local]   = h0; ((uint32_t*)hi)[2*local+1] = h1;
    ((uint32_t*)lo)[2*local]   = l0; ((uint32_t*)lo)[2*local+1] = l1;
}

// ---------------- mma.sync bf16x3 GEMM core: 128x256x32, 512 thr, 3-stage ---
#define BKG     32
#define LDT2    80                       // bytes per smem row
#define OA_L    10240                    // Ah 128*80
#define OW_H    20480
#define OW_L    40960                    // + Wh 256*80
#define STAGE_B 61440
#define SMEM_GEMM (3*STAGE_B)            // 184320 B

__device__ __forceinline__ void gemm_core(
    const __nv_bfloat16* __restrict__ A, const __nv_bfloat16* __restrict__ W,
    uint32_t sb, int m0, int n0, int tid, float acc[2][8][4])
{
    const int warp = tid >> 5, lane = tid & 31;
    const int wm = warp >> 2, wn = warp & 3;

    // per-thread loader: 6 x 16B chunks per stage
    uint32_t soff[6]; const __nv_bfloat16* gsrc[6];
    #pragma unroll
    for (int i = 0; i < 6; i++) {
        int id = tid + i * 512;                  // 0..3071
        if (id < 1024) {                         // Ah / Al
            int half = id >> 9, idx = id & 511;
            int row = idx >> 2, c = idx & 3;
            soff[i] = (uint32_t)(half * OA_L + row * LDT2 + c * 16);
            gsrc[i] = A + (size_t)half * AOFF + (size_t)(m0 + row) * D_M + c * 8;
        } else {                                 // Wh / Wl
            int rid = id - 1024;
            int half = rid >> 10, idx = rid & 1023;
            int row = idx >> 2, c = idx & 3;
            soff[i] = (uint32_t)(OW_H + half * (OW_L - OW_H) + row * LDT2 + c * 16);
            gsrc[i] = W + (size_t)half * WOFF + (size_t)(n0 + row) * D_M + c * 8;
        }
    }

    #pragma unroll
    for (int mi = 0; mi < 2; mi++)
        #pragma unroll
        for (int ni = 0; ni < 8; ni++)
            #pragma unroll
            for (int r = 0; r < 4; r++) acc[mi][ni][r] = 0.f;

    const int a_row  = wm * 32 + (lane & 15);
    const int a_col8 = (lane >> 4);
    const int bg = lane >> 3, b_in = lane & 7;
    const int b_row  = wn * 64 + (bg >> 1) * 8 + b_in;
    const int b_k8   = bg & 1;

    // prologue: chunks 0,1 -> stages 0,1
    #pragma unroll
    for (int p = 0; p < 2; p++) {
        const uint32_t dstg = sb + p * STAGE_B;
        #pragma unroll
        for (int i = 0; i < 6; i++)
            cp16(dstg + soff[i], gsrc[i] + p * BKG);
        CP_COMMIT();
    }

    for (int kt = 0; kt < 32; kt++) {
        CP_WAIT1();
        __syncthreads();                 // single barrier per iteration

        // prefetch kt+2 into stage (kt+2)%3 (consumed at kt-1, safe now)
        if (kt < 30) {
            const int kn = kt + 2;
            const uint32_t dstg = sb + (uint32_t)(kn % 3) * STAGE_B;
            #pragma unroll
            for (int i = 0; i < 6; i++)
                cp16(dstg + soff[i], gsrc[i] + kn * BKG);
        }
        CP_COMMIT();

        const uint32_t stg = sb + (uint32_t)(kt % 3) * STAGE_B;
        #pragma unroll
        for (int kk = 0; kk < 2; kk++) {
            const uint32_t acol = (uint32_t)((kk * 16 + a_col8 * 8) * 2);
            const uint32_t bcol = (uint32_t)((kk * 16 + b_k8 * 8) * 2);
            uint32_t ah[2][4], al[2][4], wh_[4][4], wl_[4][4];
            #pragma unroll
            for (int mi = 0; mi < 2; mi++)
                ldsm4(ah[mi], stg + (a_row + mi*16) * LDT2 + acol);
            #pragma unroll
            for (int pi = 0; pi < 4; pi++)
                ldsm4(wh_[pi], stg + OW_H + (b_row + pi*16) * LDT2 + bcol);
            #pragma unroll
            for (int mi = 0; mi < 2; mi++)
                #pragma unroll
                for (int ni = 0; ni < 8; ni++)
                    mma16816(acc[mi][ni], ah[mi],
                             wh_[ni>>1][(ni&1)*2], wh_[ni>>1][(ni&1)*2+1]);
            #pragma unroll
            for (int mi = 0; mi < 2; mi++)
                ldsm4(al[mi], stg + OA_L + (a_row + mi*16) * LDT2 + acol);
            #pragma unroll
            for (int mi = 0; mi < 2; mi++)
                #pragma unroll
                for (int ni = 0; ni < 8; ni++)
                    mma16816(acc[mi][ni], al[mi],
                             wh_[ni>>1][(ni&1)*2], wh_[ni>>1][(ni&1)*2+1]);
            #pragma unroll
            for (int pi = 0; pi < 4; pi++)
                ldsm4(wl_[pi], stg + OW_L + (b_row + pi*16) * LDT2 + bcol);
            #pragma unroll
            for (int mi = 0; mi < 2; mi++)
                #pragma unroll
                for (int ni = 0; ni < 8; ni++)
                    mma16816(acc[mi][ni], ah[mi],
                             wl_[ni>>1][(ni&1)*2], wl_[ni>>1][(ni&1)*2+1]);
        }
    }
}

// fused QKV: grid (64, 4, 3)
__global__ void __launch_bounds__(512, 1) gemm_qkv(
    const __nv_bfloat16* __restrict__ A, const __nv_bfloat16* __restrict__ w2b,
    const float* __restrict__ bq, const float* __restrict__ bk,
    const float* __restrict__ bv, float qscale)
{
    extern __shared__ __align__(128) char smem[];
    const int tid = threadIdx.x, warp = tid >> 5, lane = tid & 31;
    const int wm = warp >> 2, wn = warp & 3;
    const int m0 = blockIdx.x * 128, n0 = blockIdx.y * 256;
    const int z = blockIdx.z;
    const __nv_bfloat16* W = w2b + (size_t)z * 2 * WOFF;
    const float* bias = (z == 0) ? bq : (z == 1) ? bk : bv;
    __nv_bfloat16* dsth = (z == 0) ? g_qh : (z == 1) ? g_kh : g_vh;
    __nv_bfloat16* dstl = (z == 0) ? g_ql : (z == 1) ? g_kl : g_vl;
    const float outscale = (z == 0) ? qscale : 1.0f;

    float acc[2][8][4];
    gemm_core(A, W, smem_u32(smem), m0, n0, tid, acc);

    #pragma unroll
    for (int mi = 0; mi < 2; mi++) {
        #pragma unroll
        for (int ni = 0; ni < 8; ni++) {
            const int m_a = m0 + wm*32 + mi*16 + (lane >> 2);
            const int n_a = n0 + wn*64 + ni*8 + (lane & 3)*2;
            const float b0 = bias[n_a], b1 = bias[n_a + 1];
            const float v00 = (acc[mi][ni][0] + b0) * outscale;
            const float v01 = (acc[mi][ni][1] + b1) * outscale;
            const float v10 = (acc[mi][ni][2] + b0) * outscale;
            const float v11 = (acc[mi][ni][3] + b1) * outscale;
            const int h = n_a >> 6, d = n_a & 63;
            const int b  = m_a >> 11, s  = m_a & 2047;
            const int b2 = (m_a+8) >> 11, s2 = (m_a+8) & 2047;
            const size_t i0 = (((size_t)(b *NH + h))*SEQ + s )*HD + d;
            const size_t i1 = (((size_t)(b2*NH + h))*SEQ + s2)*HD + d;
            uint32_t hi, lo;
            psplit(v00, v01, hi, lo);
            *(uint32_t*)(dsth + i0) = hi; *(uint32_t*)(dstl + i0) = lo;
            psplit(v10, v11, hi, lo);
            *(uint32_t*)(dsth + i1) = hi; *(uint32_t*)(dstl + i1) = lo;
        }
    }
}

// final projection: fp32 output [M, D]
__global__ void __launch_bounds__(512, 1) gemm_out(
    const __nv_bfloat16* __restrict__ A, const __nv_bfloat16* __restrict__ W,
    const float* __restrict__ bias, float* __restrict__ fdst)
{
    extern __shared__ __align__(128) char smem[];
    const int tid = threadIdx.x, warp = tid >> 5, lane = tid & 31;
    const int wm = warp >> 2, wn = warp & 3;
    const int m0 = blockIdx.x * 128, n0 = blockIdx.y * 256;

    float acc[2][8][4];
    gemm_core(A, W, smem_u32(smem), m0, n0, tid, acc);

    #pragma unroll
    for (int mi = 0; mi < 2; mi++) {
        #pragma unroll
        for (int ni = 0; ni < 8; ni++) {
            const int m_a = m0 + wm*32 + mi*16 + (lane >> 2);
            const int n_a = n0 + wn*64 + ni*8 + (lane & 3)*2;
            const float b0 = bias[n_a], b1 = bias[n_a + 1];
            *(float2*)&fdst[(size_t)m_a     * D_M + n_a] =
                make_float2(acc[mi][ni][0] + b0, acc[mi][ni][1] + b1);
            *(float2*)&fdst[(size_t)(m_a+8) * D_M + n_a] =
                make_float2(acc[mi][ni][2] + b0, acc[mi][ni][3] + b1);
        }
    }
}

// ---------------- flash attention, bf16x3 mma.sync, 2 CTA/SM ----------------
#define ALDB 144
#define SM_Q    0
#define SM_QL   (128*ALDB)
#define SM_KV   (2*128*ALDB)
#define STG_SZ  (4*64*ALDB)
#define AKH     0
#define AKL     (64*ALDB)
#define AVH     (2*64*ALDB)
#define AVL     (3*64*ALDB)
#define ATTN_SMEM (SM_KV + 2*STG_SZ)   // 110592 B

__device__ __forceinline__ void load_kv_tile(uint32_t dst, size_t gbase,
                                             int k0, int tid)
{
    #pragma unroll
    for (int i = 0; i < 2; i++) {
        int c = tid + i * 256;
        int r = c >> 3, c16 = c & 7;
        const size_t go = gbase + (size_t)(k0 + r) * HD + c16 * 8;
        const uint32_t so = (uint32_t)(r * ALDB + c16 * 16);
        cp16(dst + AKH + so, g_kh + go);
        cp16(dst + AKL + so, g_kl + go);
        cp16(dst + AVH + so, g_vh + go);
        cp16(dst + AVL + so, g_vl + go);
    }
}

__global__ void __launch_bounds__(256, 2) attn_mma()
{
    extern __shared__ __align__(128) char smc[];
    const int tid = threadIdx.x, lane = tid & 31, warp = tid >> 5;
    const int qt = (int)gridDim.x - 1 - (int)blockIdx.x;   // long CTAs first
    const int h = blockIdx.y, b = blockIdx.z;
    const int q0 = qt * 128;
    const size_t base = ((size_t)(b*NH + h)) * SEQ * HD;
    const uint32_t sb = smem_u32(smc);
    const int nkt = 2*qt + 2;

    #pragma unroll
    for (int i = 0; i < 4; i++) {
        int c = tid + i * 256;
        int r = c >> 3, c16 = c & 7;
        const size_t go = base + (size_t)(q0 + r) * HD + c16 * 8;
        cp16(sb + SM_Q  + (uint32_t)(r*ALDB + c16*16), g_qh + go);
        cp16(sb + SM_QL + (uint32_t)(r*ALDB + c16*16), g_ql + go);
    }
    load_kv_tile(sb + SM_KV, base, 0, tid);
    CP_COMMIT();

    float sf[8][4], acc[8][4];
    #pragma unroll
    for (int j = 0; j < 8; j++)
        #pragma unroll
        for (int r = 0; r < 4; r++) acc[j][r] = 0.f;
    float m0 = -1e30f, m1 = -1e30f, l0 = 0.f, l1 = 0.f;

    const int g = lane >> 2, tig = lane & 3;
    const int qr = warp * 16;
    const int gr0 = q0 + qr + g;

    const uint32_t aQoff = (uint32_t)((qr + (lane & 15)) * ALDB + ((lane >> 4) * 8) * 2);
    const uint32_t bKoff = (uint32_t)((((lane >> 4) & 1) * 8 + (lane & 7)) * ALDB
                                      + (((lane >> 3) & 1) * 8) * 2);
    const uint32_t vToff = (uint32_t)(((lane & 7) + ((lane >> 3) & 1) * 8) * ALDB
                                      + ((lane >> 4) * 8) * 2);

    for (int kt = 0; kt < nkt; kt++) {
        CP_WAIT0();
        __syncthreads();
        const uint32_t stg = sb + SM_KV + (uint32_t)(kt & 1) * STG_SZ;
        if (kt + 1 < nkt)
            load_kv_tile(sb + SM_KV + (uint32_t)((kt+1) & 1) * STG_SZ,
                         base, (kt+1)*64, tid);
        CP_COMMIT();

        #pragma unroll
        for (int j = 0; j < 8; j++)
            #pragma unroll
            for (int r = 0; r < 4; r++) sf[j][r] = 0.f;

        #pragma unroll
        for (int t = 0; t < 4; t++) {
            uint32_t ah[4], al[4];
            ldsm4(ah, sb + SM_Q  + aQoff + t*32);
            ldsm4(al, sb + SM_QL + aQoff + t*32);
            #pragma unroll
            for (int nn = 0; nn < 4; nn++) {
                uint32_t bh[4], bl[4];
                ldsm4(bh, stg + AKH + (uint32_t)(nn*16)*ALDB + bKoff + t*32);
                mma16816(sf[2*nn],   ah, bh[0], bh[1]);
                mma16816(sf[2*nn+1], ah, bh[2], bh[3]);
                mma16816(sf[2*nn],   al, bh[0], bh[1]);
                mma16816(sf[2*nn+1], al, bh[2], bh[3]);
                ldsm4(bl, stg + AKL + (uint32_t)(nn*16)*ALDB + bKoff + t*32);
                mma16816(sf[2*nn],   ah, bl[0], bl[1]);
                mma16816(sf[2*nn+1], ah, bl[2], bl[3]);
            }
        }

        const int k0 = kt * 64;
        if (k0 + 63 > gr0) {
            #pragma unroll
            for (int j = 0; j < 8; j++) {
                const int kc = k0 + 8*j + 2*tig;
                if (kc     > gr0)     sf[j][0] = -1e30f;
                if (kc + 1 > gr0)     sf[j][1] = -1e30f;
                if (kc     > gr0 + 8) sf[j][2] = -1e30f;
                if (kc + 1 > gr0 + 8) sf[j][3] = -1e30f;
            }
        }

        float mx0 = -1e30f, mx1 = -1e30f;
        #pragma unroll
        for (int j = 0; j < 8; j++) {
            mx0 = fmaxf(mx0, fmaxf(sf[j][0], sf[j][1]));
            mx1 = fmaxf(mx1, fmaxf(sf[j][2], sf[j][3]));
        }
        mx0 = fmaxf(mx0, __shfl_xor_sync(0xffffffffu, mx0, 1));
        mx0 = fmaxf(mx0, __shfl_xor_sync(0xffffffffu, mx0, 2));
        mx1 = fmaxf(mx1, __shfl_xor_sync(0xffffffffu, mx1, 1));
        mx1 = fmaxf(mx1, __shfl_xor_sync(0xffffffffu, mx1, 2));
        const float mn0 = fmaxf(m0, mx0), mn1 = fmaxf(m1, mx1);
        const float a0 = fexp2(m0 - mn0), a1 = fexp2(m1 - mn1);
        m0 = mn0; m1 = mn1;
        float s0 = 0.f, s1 = 0.f;
        #pragma unroll
        for (int j = 0; j < 8; j++) {
            sf[j][0] = fexp2(sf[j][0] - mn0); s0 += sf[j][0];
            sf[j][1] = fexp2(sf[j][1] - mn0); s0 += sf[j][1];
            sf[j][2] = fexp2(sf[j][2] - mn1); s1 += sf[j][2];
            sf[j][3] = fexp2(sf[j][3] - mn1); s1 += sf[j][3];
        }
        s0 += __shfl_xor_sync(0xffffffffu, s0, 1);
        s0 += __shfl_xor_sync(0xffffffffu, s0, 2);
        s1 += __shfl_xor_sync(0xffffffffu, s1, 1);
        s1 += __shfl_xor_sync(0xffffffffu, s1, 2);
        l0 = l0 * a0 + s0; l1 = l1 * a1 + s1;
        #pragma unroll
        for (int j = 0; j < 8; j++) {
            acc[j][0] *= a0; acc[j][1] *= a0;
            acc[j][2] *= a1; acc[j][3] *= a1;
        }

        #pragma unroll
        for (int t = 0; t < 4; t++) {
            uint32_t ph[4], pl[4];
            psplit(sf[2*t][0],   sf[2*t][1],   ph[0], pl[0]);
            psplit(sf[2*t][2],   sf[2*t][3],   ph[1], pl[1]);
            psplit(sf[2*t+1][0], sf[2*t+1][1], ph[2], pl[2]);
            psplit(sf[2*t+1][2], sf[2*t+1][3], ph[3], pl[3]);
            #pragma unroll
            for (int nn = 0; nn < 4; nn++) {
                uint32_t vh[4], vl[4];
                ldsm4t(vh, stg + AVH + (uint32_t)(t*16)*ALDB + vToff + nn*32);
                mma16816(acc[2*nn],   ph, vh[0], vh[1]);
                mma16816(acc[2*nn+1], ph, vh[2], vh[3]);
                mma16816(acc[2*nn],   pl, vh[0], vh[1]);
                mma16816(acc[2*nn+1], pl, vh[2], vh[3]);
                ldsm4t(vl, stg + AVL + (uint32_t)(t*16)*ALDB + vToff + nn*32);
                mma16816(acc[2*nn],   ph, vl[0], vl[1]);
                mma16816(acc[2*nn+1], ph, vl[2], vl[3]);
            }
        }
    }

    const float il0 = 1.0f / l0, il1 = 1.0f / l1;
    const size_t o0 = ((size_t)(b*SEQ + gr0)) * D_M + h*HD;
    const size_t o1 = o0 + (size_t)8 * D_M;
    #pragma unroll
    for (int j = 0; j < 8; j++) {
        const int c = 8*j + 2*tig;
        uint32_t hi, lo;
        psplit(acc[j][0]*il0, acc[j][1]*il0, hi, lo);
        *(uint32_t*)(g_y2 + o0 + c) = hi; *(uint32_t*)(g_y2 + AOFF + o0 + c) = lo;
        psplit(acc[j][2]*il1, acc[j][3]*il1, hi, lo);
        *(uint32_t*)(g_y2 + o1 + c) = hi; *(uint32_t*)(g_y2 + AOFF + o1 + c) = lo;
    }
}

// ---------------------------------------------------------------------------
extern "C" void kernel_launch(void* const* d_in, const int* in_sizes, int n_in,
                              void* d_out, int out_size)
{
    const float* x  = (const float*)d_in[0];
    const float* Wq = (const float*)d_in[1];
    const float* bq = (const float*)d_in[2];
    const float* Wk = (const float*)d_in[3];
    const float* bk = (const float*)d_in[4];
    const float* Wv = (const float*)d_in[5];
    const float* bv = (const float*)d_in[6];
    const float* Wo = (const float*)d_in[7];
    const float* bo = (const float*)d_in[8];
    float* out = (float*)d_out;

    __nv_bfloat16 *x2, *y2, *w2;
    cudaGetSymbolAddress((void**)&x2, g_x2);
    cudaGetSymbolAddress((void**)&y2, g_y2);
    cudaGetSymbolAddress((void**)&w2, g_w2);

    const int n4x = MTOT * D_M / 4;
    split_kernel<<<n4x/256, 256>>>(x, x2, x2 + AOFF, n4x);
    split_w_kernel<<<4*262144/256, 256>>>(Wq, Wk, Wv, Wo, w2);

    cudaFuncSetAttribute(gemm_qkv,
                         cudaFuncAttributeMaxDynamicSharedMemorySize, SMEM_GEMM);
    cudaFuncSetAttribute(gemm_out,
                         cudaFuncAttributeMaxDynamicSharedMemorySize, SMEM_GEMM);
    cudaFuncSetAttribute(attn_mma,
                         cudaFuncAttributeMaxDynamicSharedMemorySize, ATTN_SMEM);

    const float qscale = 0.125f * 1.4426950408889634f;
    gemm_qkv<<<dim3(MTOT/128, D_M/256, 3), 512, SMEM_GEMM>>>(
        x2, w2, bq, bk, bv, qscale);

    attn_mma<<<dim3(SEQ/128, NH, BATCH), 256, ATTN_SMEM>>>();

    gemm_out<<<dim3(MTOT/128, D_M/256), 512, SMEM_GEMM>>>(
        y2, w2 + 3*2*WOFF, bo, out);
}